// round 3
// baseline (speedup 1.0000x reference)
#include <cuda_runtime.h>
#include <math.h>

#define B_ 2
#define L_ 1024
#define D_ 768
#define H_ 12
#define HD_ 64
#define FF_ 3072
#define V_ 32000
#define NL_ 2
#define TOK_BOS 1
#define TOK_SEP 2
#define WIN_ 512
#define EPS_ 1e-5f
#define M_ (B_ * L_) /* 2048 rows */

// ---------------- scratch (static device globals; no allocation) ------------
__device__ float g_x[M_ * D_];
__device__ float g_h[M_ * D_];
__device__ float g_qkv[M_ * 3 * D_];
__device__ float g_y[M_ * D_];
__device__ float g_ff[M_ * FF_];
__device__ float g_sc[(size_t)B_ * H_ * L_ * L_];   // 100.7 MB
__device__ int   g_seg[B_ * L_];
__device__ int   g_gkey[B_ * L_];
__device__ int   g_valid[B_ * L_];

// ---------------- embedding -------------------------------------------------
__global__ void k_embed(const int* __restrict__ tokens, const int* __restrict__ types,
                        const float* __restrict__ tok_emb, const float* __restrict__ type_emb,
                        const float* __restrict__ pos_emb) {
    int idx = blockIdx.x * blockDim.x + threadIdx.x;
    if (idx >= M_ * D_) return;
    int d = idx % D_;
    int bl = idx / D_;
    int l = bl % L_;
    g_x[idx] = tok_emb[(size_t)tokens[bl] * D_ + d]
             + type_emb[(size_t)types[bl] * D_ + d]
             + pos_emb[(size_t)l * D_ + d];
}

// ---------------- mask metadata ----------------------------------------------
__global__ void k_maskprep(const int* __restrict__ tokens, const int* __restrict__ attn_mask) {
    int b = threadIdx.x;
    if (b >= B_) return;
    int seg = 0;
    for (int l = 0; l < L_; l++) {
        int i = b * L_ + l;
        int va = attn_mask[i] != 0;
        int tok = tokens[i];
        int is_sep = (tok == TOK_SEP) && va;
        seg += is_sep;
        g_seg[i] = seg;
        g_gkey[i] = (((tok == TOK_BOS) && va) || is_sep) ? 1 : 0;
        g_valid[i] = va;
    }
}

// ---------------- layernorm --------------------------------------------------
__global__ __launch_bounds__(256)
void k_ln(const float* __restrict__ x, const float* __restrict__ sc,
          const float* __restrict__ bi, float* __restrict__ out) {
    int row = blockIdx.x;
    const float* xr = x + (size_t)row * D_;
    int t = threadIdx.x;
    float v0 = xr[t], v1 = xr[t + 256], v2 = xr[t + 512];
    float s = v0 + v1 + v2;
    float ss = v0 * v0 + v1 * v1 + v2 * v2;
    __shared__ float rs[8], rq[8];
#pragma unroll
    for (int o = 16; o > 0; o >>= 1) {
        s  += __shfl_xor_sync(0xffffffffu, s, o);
        ss += __shfl_xor_sync(0xffffffffu, ss, o);
    }
    if ((t & 31) == 0) { rs[t >> 5] = s; rq[t >> 5] = ss; }
    __syncthreads();
    if (t < 32) {
        float a = (t < 8) ? rs[t] : 0.f;
        float q = (t < 8) ? rq[t] : 0.f;
#pragma unroll
        for (int o = 4; o > 0; o >>= 1) {
            a += __shfl_xor_sync(0xffffffffu, a, o);
            q += __shfl_xor_sync(0xffffffffu, q, o);
        }
        if (t == 0) { rs[0] = a; rq[0] = q; }
    }
    __syncthreads();
    float mean = rs[0] * (1.0f / D_);
    float var  = rq[0] * (1.0f / D_) - mean * mean;
    float inv = rsqrtf(var + EPS_);
    float* orow = out + (size_t)row * D_;
    orow[t]       = (v0 - mean) * inv * sc[t]       + bi[t];
    orow[t + 256] = (v1 - mean) * inv * sc[t + 256] + bi[t + 256];
    orow[t + 512] = (v2 - mean) * inv * sc[t + 512] + bi[t + 512];
}

// ---------------- TF32 tensor-core GEMM NT (fragment-major smem) ------------
__device__ __forceinline__ unsigned f2tf(float x) {
    unsigned r;
    asm("cvt.rna.tf32.f32 %0, %1;" : "=r"(r) : "f"(x));
    return r;
}

__device__ __forceinline__ void mma8(float* c, const unsigned* a, const unsigned* b) {
    asm volatile(
        "mma.sync.aligned.m16n8k8.row.col.f32.tf32.tf32.f32 "
        "{%0,%1,%2,%3}, {%4,%5,%6,%7}, {%8,%9}, {%0,%1,%2,%3};\n"
        : "+f"(c[0]), "+f"(c[1]), "+f"(c[2]), "+f"(c[3])
        : "r"(a[0]), "r"(a[1]), "r"(a[2]), "r"(a[3]), "r"(b[0]), "r"(b[1]));
}

// store one (row, 8-col half) into fragment-major swizzled smem, as 4x STS.64
// region layout: [ks][t16][lane'(32)][reg(4)]; quad of lane = the 4 mma regs.
// reg = 2*(rr>=8) + (col>=4); quad order = {a0, a2, a1, a3} equivalent.
__device__ __forceinline__ void stash(unsigned* dst, int t16, int rr, int ks,
                                      float4 lo, float4 hi, int NT) {
    const float* l = (const float*)&lo;
    const float* h = (const float*)&hi;
    int base = (ks * NT + t16) * 128 + ((rr >> 3) << 1);
    int rbit = (rr & 7) * 4;
    int add = (rbit >> 3) + ks;  // (lane>>3)+ks with lane=rbit+j, j<4
#pragma unroll
    for (int j = 0; j < 4; j++) {
        int lane = rbit + j;
        int lp = (lane & 28) | ((lane + add) & 3);
        uint2 v;
        v.x = f2tf(l[j]);
        v.y = f2tf(h[j]);
        *(uint2*)(dst + base + lp * 4) = v;
    }
}

template <int BN>
__global__ void __launch_bounds__(256, BN == 128 ? 2 : 1)
k_mma(const float* __restrict__ A, const float* __restrict__ Bw,
      float* __restrict__ C, int M, int N, int K,
      const float* __restrict__ bias, const float* __restrict__ resid,
      int dogelu) {
    constexpr int WN  = BN / 4;       // warp N tile (2x4 warps, warp = 64 x WN)
    constexpr int NI8 = WN / 8;       // n8 mma tiles per warp
    constexpr int NTB = BN / 16;      // n16 tiles per block
    constexpr int REP = BN / 128;     // B row reps per thread
    constexpr int ASZ = 2 * 8 * 128;  // floats per stage
    constexpr int BSZ = 2 * NTB * 128;
    __shared__ unsigned sA[2][ASZ];
    __shared__ unsigned sB[2][BSZ];

    const int bm = blockIdx.y * 128, bn = blockIdx.x * BN;
    const int tid = threadIdx.x;
    const int lane = tid & 31, warp = tid >> 5;
    const int wm = (warp & 1) * 64, wn = (warp >> 1) * WN;
    const int gid = lane >> 2, cid = lane & 3;
    const int lr = tid >> 1;          // load row 0..127
    const int kh = tid & 1;           // which 8-col half (=ks)
    const float* Ag = A + (size_t)(bm + lr) * K + kh * 8;
    const float* Bg = Bw + (size_t)(bn + lr) * K + kh * 8;

    float acc[4][NI8][4];
#pragma unroll
    for (int i = 0; i < 4; i++)
#pragma unroll
        for (int j = 0; j < NI8; j++)
#pragma unroll
            for (int r = 0; r < 4; r++) acc[i][j][r] = 0.f;

    // prologue: fill stage 0
    {
        float4 al = *(const float4*)(Ag);
        float4 ah = *(const float4*)(Ag + 4);
        stash(sA[0], lr >> 4, lr & 15, kh, al, ah, 8);
#pragma unroll
        for (int rep = 0; rep < REP; rep++) {
            const float* bp = Bg + (size_t)rep * 128 * K;
            float4 bl = *(const float4*)(bp);
            float4 bh = *(const float4*)(bp + 4);
            stash(sB[0], (lr >> 4) + rep * 8, lr & 15, kh, bl, bh, NTB);
        }
    }
    __syncthreads();

    const int nk = K >> 4;
    for (int kt = 0; kt < nk; kt++) {
        const int s = kt & 1;
        float4 pal, pah, pbl[REP], pbh[REP];
        if (kt + 1 < nk) {
            const float* An = Ag + (kt + 1) * 16;
            pal = *(const float4*)(An);
            pah = *(const float4*)(An + 4);
#pragma unroll
            for (int rep = 0; rep < REP; rep++) {
                const float* bp = Bg + (size_t)rep * 128 * K + (kt + 1) * 16;
                pbl[rep] = *(const float4*)(bp);
                pbh[rep] = *(const float4*)(bp + 4);
            }
        }
#pragma unroll
        for (int ks = 0; ks < 2; ks++) {
            const int lp = (lane & 28) | ((lane + (lane >> 3) + ks) & 3);
            unsigned af[4][4];
#pragma unroll
            for (int mi = 0; mi < 4; mi++) {
                uint4 q = *(const uint4*)&sA[s][((ks * 8 + (wm >> 4) + mi) * 32 + lp) * 4];
                af[mi][0] = q.x; af[mi][1] = q.z; af[mi][2] = q.y; af[mi][3] = q.w;
            }
            unsigned bf[NI8][2];
#pragma unroll
            for (int nt = 0; nt < NI8 / 2; nt++) {
                uint4 q = *(const uint4*)&sB[s][((ks * NTB + (wn >> 4) + nt) * 32 + lp) * 4];
                bf[2 * nt][0] = q.x; bf[2 * nt][1] = q.y;
                bf[2 * nt + 1][0] = q.z; bf[2 * nt + 1][1] = q.w;
            }
#pragma unroll
            for (int mi = 0; mi < 4; mi++)
#pragma unroll
                for (int ni = 0; ni < NI8; ni++)
                    mma8(acc[mi][ni], af[mi], bf[ni]);
        }
        if (kt + 1 < nk) {
            const int sn = s ^ 1;
            stash(sA[sn], lr >> 4, lr & 15, kh, pal, pah, 8);
#pragma unroll
            for (int rep = 0; rep < REP; rep++)
                stash(sB[sn], (lr >> 4) + rep * 8, lr & 15, kh, pbl[rep], pbh[rep], NTB);
            __syncthreads();
        }
    }

    // epilogue
#pragma unroll
    for (int mi = 0; mi < 4; mi++) {
        int r0 = bm + wm + mi * 16 + gid;
#pragma unroll
        for (int ni = 0; ni < NI8; ni++) {
            int c0 = bn + wn + ni * 8 + 2 * cid;
            float v00 = acc[mi][ni][0], v01 = acc[mi][ni][1];
            float v10 = acc[mi][ni][2], v11 = acc[mi][ni][3];
            if (bias) {
                float b0v = bias[c0], b1v = bias[c0 + 1];
                v00 += b0v; v01 += b1v; v10 += b0v; v11 += b1v;
            }
            if (resid) {
                const float* rr0 = resid + (size_t)r0 * N + c0;
                const float* rr1 = resid + (size_t)(r0 + 8) * N + c0;
                v00 += rr0[0]; v01 += rr0[1]; v10 += rr1[0]; v11 += rr1[1];
            }
            if (dogelu) {
                v00 = 0.5f * v00 * (1.0f + erff(v00 * 0.70710678118654752f));
                v01 = 0.5f * v01 * (1.0f + erff(v01 * 0.70710678118654752f));
                v10 = 0.5f * v10 * (1.0f + erff(v10 * 0.70710678118654752f));
                v11 = 0.5f * v11 * (1.0f + erff(v11 * 0.70710678118654752f));
            }
            *(float2*)&C[(size_t)r0 * N + c0]       = make_float2(v00, v01);
            *(float2*)&C[(size_t)(r0 + 8) * N + c0] = make_float2(v10, v11);
        }
    }
}

// ---------------- attention scores: S = Q K^T * scale + box-mask ------------
__global__ __launch_bounds__(256)
void k_scores(const float* __restrict__ qkv) {
    const int bh = blockIdx.z;
    const int b = bh / H_, h = bh % H_;
    const int i0 = blockIdx.y * 64, j0 = blockIdx.x * 64;
    const int t = threadIdx.x;
    const int tm = (t >> 4) * 4, tn = (t & 15) * 4;
    const size_t sbase = ((size_t)bh * L_ + i0) * L_ + j0;

    if (j0 > i0 + 63) { // fully above the diagonal: all masked
#pragma unroll
        for (int i = 0; i < 4; i++)
#pragma unroll
            for (int j = 0; j < 4; j++)
                g_sc[sbase + (size_t)(tm + i) * L_ + tn + j] = -1e30f;
        return;
    }

    __shared__ float Qs[64][65];
    __shared__ float Ks[64][65];
    const float* qb = qkv + (size_t)(b * L_ + i0) * (3 * D_) + h * HD_;
    const float* kb = qkv + (size_t)(b * L_ + j0) * (3 * D_) + D_ + h * HD_;
    for (int idx = t; idx < 64 * 64; idx += 256) {
        int r = idx >> 6, c = idx & 63;
        Qs[r][c] = qb[(size_t)r * (3 * D_) + c];
        Ks[r][c] = kb[(size_t)r * (3 * D_) + c];
    }
    __syncthreads();

    float acc[4][4] = {};
#pragma unroll 8
    for (int d = 0; d < 64; d++) {
        float q[4], k[4];
#pragma unroll
        for (int i = 0; i < 4; i++) { q[i] = Qs[tm + i][d]; k[i] = Ks[tn + i][d]; }
#pragma unroll
        for (int i = 0; i < 4; i++)
#pragma unroll
            for (int j = 0; j < 4; j++) acc[i][j] += q[i] * k[j];
    }

    const int* segb = g_seg + b * L_;
    const int* gkb  = g_gkey + b * L_;
    const int* vab  = g_valid + b * L_;
#pragma unroll
    for (int i = 0; i < 4; i++) {
        int gi = i0 + tm + i;
        int si = segb[gi];
#pragma unroll
        for (int j = 0; j < 4; j++) {
            int gj = j0 + tn + j;
            float v = acc[i][j] * 0.125f; // 1/sqrt(64)
            bool allowed = (gj <= gi) && vab[gj] &&
                           (segb[gj] == si || gkb[gj] || (gi - gj) <= WIN_);
            g_sc[sbase + (size_t)(tm + i) * L_ + tn + j] = allowed ? v : -1e30f;
        }
    }
}

// ---------------- row softmax over L=1024 -----------------------------------
__global__ __launch_bounds__(256)
void k_softmax() {
    size_t row = blockIdx.x;
    float* p = g_sc + row * L_;
    int t = threadIdx.x;
    float v[4];
    float mx = -1e30f;
#pragma unroll
    for (int i = 0; i < 4; i++) { v[i] = p[i * 256 + t]; mx = fmaxf(mx, v[i]); }
    __shared__ float rmax[8], rsum[8];
#pragma unroll
    for (int o = 16; o > 0; o >>= 1) mx = fmaxf(mx, __shfl_xor_sync(0xffffffffu, mx, o));
    if ((t & 31) == 0) rmax[t >> 5] = mx;
    __syncthreads();
    if (t < 32) {
        float m = (t < 8) ? rmax[t] : -1e30f;
#pragma unroll
        for (int o = 4; o > 0; o >>= 1) m = fmaxf(m, __shfl_xor_sync(0xffffffffu, m, o));
        if (t == 0) rmax[0] = m;
    }
    __syncthreads();
    float bm = rmax[0];
    float s = 0.f;
#pragma unroll
    for (int i = 0; i < 4; i++) { v[i] = __expf(v[i] - bm); s += v[i]; }
#pragma unroll
    for (int o = 16; o > 0; o >>= 1) s += __shfl_xor_sync(0xffffffffu, s, o);
    if ((t & 31) == 0) rsum[t >> 5] = s;
    __syncthreads();
    if (t < 32) {
        float a = (t < 8) ? rsum[t] : 0.f;
#pragma unroll
        for (int o = 4; o > 0; o >>= 1) a += __shfl_xor_sync(0xffffffffu, a, o);
        if (t == 0) rsum[0] = a;
    }
    __syncthreads();
    float inv = 1.0f / rsum[0];
#pragma unroll
    for (int i = 0; i < 4; i++) p[i * 256 + t] = v[i] * inv;
}

// ---------------- y = P @ V --------------------------------------------------
__global__ __launch_bounds__(256)
void k_av(const float* __restrict__ qkv) {
    const int bh = blockIdx.y;
    const int b = bh / H_, h = bh % H_;
    const int i0 = blockIdx.x * 64;
    const int t = threadIdx.x;
    const int tm = (t >> 4) * 4, tn = (t & 15) * 4;
    __shared__ float Ps[64][65];
    __shared__ float Vs[64][65];
    float acc[4][4] = {};
    const float* vb = qkv + (size_t)b * L_ * 3 * D_ + 2 * D_ + h * HD_;
    for (int j0 = 0; j0 <= i0 + 63; j0 += 64) {
        for (int idx = t; idx < 64 * 64; idx += 256) {
            int r = idx >> 6, c = idx & 63;
            Ps[r][c] = g_sc[((size_t)bh * L_ + i0 + r) * L_ + j0 + c];
            Vs[r][c] = vb[(size_t)(j0 + r) * 3 * D_ + c];
        }
        __syncthreads();
#pragma unroll 4
        for (int jj = 0; jj < 64; jj++) {
            float pr[4], vv[4];
#pragma unroll
            for (int i = 0; i < 4; i++) { pr[i] = Ps[tm + i][jj]; vv[i] = Vs[jj][tn + i]; }
#pragma unroll
            for (int i = 0; i < 4; i++)
#pragma unroll
                for (int j = 0; j < 4; j++) acc[i][j] += pr[i] * vv[j];
        }
        __syncthreads();
    }
    float* yb = g_y + (size_t)(b * L_ + i0) * D_ + h * HD_;
#pragma unroll
    for (int i = 0; i < 4; i++)
#pragma unroll
        for (int j = 0; j < 4; j++)
            yb[(size_t)(tm + i) * D_ + tn + j] = acc[i][j];
}

// ---------------- host side --------------------------------------------------
static void gemm(const float* A, const float* Bw, float* C, int M, int N, int K,
                 const float* bias, const float* resid, bool gelu_flag) {
    if (N >= 2304 && (N % 256) == 0) {
        dim3 grid(N / 256, M / 128);
        k_mma<256><<<grid, 256>>>(A, Bw, C, M, N, K, bias, resid, gelu_flag ? 1 : 0);
    } else {
        dim3 grid(N / 128, M / 128);
        k_mma<128><<<grid, 256>>>(A, Bw, C, M, N, K, bias, resid, gelu_flag ? 1 : 0);
    }
}

extern "C" void kernel_launch(void* const* d_in, const int* in_sizes, int n_in,
                              void* d_out, int out_size) {
    const int*   tokens    = (const int*)d_in[0];
    const int*   types     = (const int*)d_in[1];
    const int*   attn_mask = (const int*)d_in[2];
    const float* tok_emb   = (const float*)d_in[3];
    const float* type_emb  = (const float*)d_in[4];
    const float* pos_emb   = (const float*)d_in[5];
    const float* qkv_w     = (const float*)d_in[6];
    const float* out_w     = (const float*)d_in[7];
    const float* ln1_s     = (const float*)d_in[8];
    const float* ln1_b     = (const float*)d_in[9];
    const float* ln2_s     = (const float*)d_in[10];
    const float* ln2_b     = (const float*)d_in[11];
    const float* ff_w1     = (const float*)d_in[12];
    const float* ff_b1     = (const float*)d_in[13];
    const float* ff_w2     = (const float*)d_in[14];
    const float* ff_b2     = (const float*)d_in[15];
    const float* lnf_s     = (const float*)d_in[16];
    const float* lnf_b     = (const float*)d_in[17];
    const float* head_w    = (const float*)d_in[18];
    float* out = (float*)d_out;

    float *x, *h, *qkv, *y, *ff;
    cudaGetSymbolAddress((void**)&x, g_x);
    cudaGetSymbolAddress((void**)&h, g_h);
    cudaGetSymbolAddress((void**)&qkv, g_qkv);
    cudaGetSymbolAddress((void**)&y, g_y);
    cudaGetSymbolAddress((void**)&ff, g_ff);

    k_embed<<<(M_ * D_ + 255) / 256, 256>>>(tokens, types, tok_emb, type_emb, pos_emb);
    k_maskprep<<<1, 32>>>(tokens, attn_mask);

    for (int l = 0; l < NL_; l++) {
        k_ln<<<M_, 256>>>(x, ln1_s + l * D_, ln1_b + l * D_, h);
        gemm(h, qkv_w + (size_t)l * 3 * D_ * D_, qkv, M_, 3 * D_, D_, nullptr, nullptr, false);
        k_scores<<<dim3(L_ / 64, L_ / 64, B_ * H_), 256>>>(qkv);
        k_softmax<<<B_ * H_ * L_, 256>>>();
        k_av<<<dim3(L_ / 64, B_ * H_), 256>>>(qkv);
        gemm(y, out_w + (size_t)l * D_ * D_, x, M_, D_, D_, nullptr, x, false);
        k_ln<<<M_, 256>>>(x, ln2_s + l * D_, ln2_b + l * D_, h);
        gemm(h, ff_w1 + (size_t)l * FF_ * D_, ff, M_, FF_, D_, ff_b1 + l * FF_, nullptr, true);
        gemm(ff, ff_w2 + (size_t)l * D_ * FF_, x, M_, D_, FF_, ff_b2 + l * D_, x, false);
    }
    k_ln<<<M_, 256>>>(x, lnf_s, lnf_b, h);
    gemm(h, head_w, out, M_, V_, D_, nullptr, nullptr, false);
}

// round 5
// speedup vs baseline: 1.1449x; 1.1449x over previous
#include <cuda_runtime.h>
#include <math.h>
#include <stdint.h>

#define B_ 2
#define L_ 1024
#define D_ 768
#define H_ 12
#define HD_ 64
#define FF_ 3072
#define V_ 32000
#define NL_ 2
#define TOK_BOS 1
#define TOK_SEP 2
#define WIN_ 512
#define EPS_ 1e-5f
#define M_ (B_ * L_) /* 2048 rows */

// ---------------- scratch (static device globals; no allocation) ------------
__device__ float g_x[M_ * D_];
__device__ float g_h[M_ * D_];
__device__ float g_qkv[M_ * 3 * D_];
__device__ float g_y[M_ * D_];
__device__ float g_ff[M_ * FF_];
__device__ float g_sc[(size_t)B_ * H_ * L_ * L_];   // 100.7 MB
__device__ int   g_seg[B_ * L_];
__device__ int   g_gkey[B_ * L_];
__device__ int   g_valid[B_ * L_];

// ---------------- embedding -------------------------------------------------
__global__ void k_embed(const int* __restrict__ tokens, const int* __restrict__ types,
                        const float* __restrict__ tok_emb, const float* __restrict__ type_emb,
                        const float* __restrict__ pos_emb) {
    int idx = blockIdx.x * blockDim.x + threadIdx.x;
    if (idx >= M_ * D_) return;
    int d = idx % D_;
    int bl = idx / D_;
    int l = bl % L_;
    g_x[idx] = tok_emb[(size_t)tokens[bl] * D_ + d]
             + type_emb[(size_t)types[bl] * D_ + d]
             + pos_emb[(size_t)l * D_ + d];
}

// ---------------- mask metadata ----------------------------------------------
__global__ void k_maskprep(const int* __restrict__ tokens, const int* __restrict__ attn_mask) {
    int b = threadIdx.x;
    if (b >= B_) return;
    int seg = 0;
    for (int l = 0; l < L_; l++) {
        int i = b * L_ + l;
        int va = attn_mask[i] != 0;
        int tok = tokens[i];
        int is_sep = (tok == TOK_SEP) && va;
        seg += is_sep;
        g_seg[i] = seg;
        g_gkey[i] = (((tok == TOK_BOS) && va) || is_sep) ? 1 : 0;
        g_valid[i] = va;
    }
}

// ---------------- layernorm --------------------------------------------------
__global__ __launch_bounds__(256)
void k_ln(const float* __restrict__ x, const float* __restrict__ sc,
          const float* __restrict__ bi, float* __restrict__ out) {
    int row = blockIdx.x;
    const float* xr = x + (size_t)row * D_;
    int t = threadIdx.x;
    float v0 = xr[t], v1 = xr[t + 256], v2 = xr[t + 512];
    float s = v0 + v1 + v2;
    float ss = v0 * v0 + v1 * v1 + v2 * v2;
    __shared__ float rs[8], rq[8];
#pragma unroll
    for (int o = 16; o > 0; o >>= 1) {
        s  += __shfl_xor_sync(0xffffffffu, s, o);
        ss += __shfl_xor_sync(0xffffffffu, ss, o);
    }
    if ((t & 31) == 0) { rs[t >> 5] = s; rq[t >> 5] = ss; }
    __syncthreads();
    if (t < 32) {
        float a = (t < 8) ? rs[t] : 0.f;
        float q = (t < 8) ? rq[t] : 0.f;
#pragma unroll
        for (int o = 4; o > 0; o >>= 1) {
            a += __shfl_xor_sync(0xffffffffu, a, o);
            q += __shfl_xor_sync(0xffffffffu, q, o);
        }
        if (t == 0) { rs[0] = a; rq[0] = q; }
    }
    __syncthreads();
    float mean = rs[0] * (1.0f / D_);
    float var  = rq[0] * (1.0f / D_) - mean * mean;
    float inv = rsqrtf(var + EPS_);
    float* orow = out + (size_t)row * D_;
    orow[t]       = (v0 - mean) * inv * sc[t]       + bi[t];
    orow[t + 256] = (v1 - mean) * inv * sc[t + 256] + bi[t + 256];
    orow[t + 512] = (v2 - mean) * inv * sc[t + 512] + bi[t + 512];
}

// ---------------- TF32 tensor-core GEMM NT + cp.async pipeline --------------
// C[M,N] = A[M,K] @ Bw[N,K]^T (+bias/+resid/gelu)
// 128x128 tile, BK=16, 256 thr = 8 warps (2M x 4N), warp tile 64x32.
// smem raw fp32 [row][k] stride 20 (conflict-free fragment reads),
// filled via cp.async 16B; cvt.rna.tf32 in registers.
__device__ __forceinline__ unsigned f2tf(float x) {
    unsigned r;
    asm("cvt.rna.tf32.f32 %0, %1;" : "=r"(r) : "f"(x));
    return r;
}
__device__ __forceinline__ uint32_t smem_u32(const void* p) {
    uint32_t a;
    asm("{ .reg .u64 t; cvta.to.shared.u64 t, %1; cvt.u32.u64 %0, t; }" : "=r"(a) : "l"(p));
    return a;
}
__device__ __forceinline__ void cpa16(uint32_t s, const void* g) {
    asm volatile("cp.async.cg.shared.global [%0], [%1], 16;" :: "r"(s), "l"(g));
}
#define CP_COMMIT() asm volatile("cp.async.commit_group;" ::: "memory")
#define CP_WAIT1()  asm volatile("cp.async.wait_group 1;" ::: "memory")
#define CP_WAIT0()  asm volatile("cp.async.wait_group 0;" ::: "memory")

__device__ __forceinline__ void mma8(float* c, const unsigned* a, const unsigned* b) {
    asm volatile(
        "mma.sync.aligned.m16n8k8.row.col.f32.tf32.tf32.f32 "
        "{%0,%1,%2,%3}, {%4,%5,%6,%7}, {%8,%9}, {%0,%1,%2,%3};\n"
        : "+f"(c[0]), "+f"(c[1]), "+f"(c[2]), "+f"(c[3])
        : "r"(a[0]), "r"(a[1]), "r"(a[2]), "r"(a[3]), "r"(b[0]), "r"(b[1]));
}

__global__ __launch_bounds__(256, 2)
void k_mma_nt(const float* __restrict__ A, const float* __restrict__ Bw,
              float* __restrict__ C, int M, int N, int K,
              const float* __restrict__ bias, const float* __restrict__ resid,
              int dogelu) {
    __shared__ float As[2][128][20];
    __shared__ float Bs[2][128][20];
    const int bm = blockIdx.y * 128, bn = blockIdx.x * 128;
    const int tid = threadIdx.x;
    const int lane = tid & 31, warp = tid >> 5;
    const int wm = (warp & 1) * 64, wn = (warp >> 1) * 32;
    const int gid = lane >> 2, cid = lane & 3;

    // loader mapping: each thread fills 2 A-chunks + 2 B-chunks of 16B
    const int lrow = tid >> 1;
    const int lk = (tid & 1) * 8;   // float offset within 16-wide k slab
    const float* Ag = A  + (size_t)(bm + lrow) * K + lk;
    const float* Bg = Bw + (size_t)(bn + lrow) * K + lk;
    const uint32_t sAd = smem_u32(&As[0][lrow][lk]);
    const uint32_t sBd = smem_u32(&Bs[0][lrow][lk]);
    const uint32_t stg = (uint32_t)(128 * 20 * sizeof(float)); // stage stride

    float acc[4][4][4];
#pragma unroll
    for (int i = 0; i < 4; i++)
#pragma unroll
        for (int j = 0; j < 4; j++)
#pragma unroll
            for (int r = 0; r < 4; r++) acc[i][j][r] = 0.f;

    // prologue: stage 0
    cpa16(sAd,      Ag);
    cpa16(sAd + 16, Ag + 4);
    cpa16(sBd,      Bg);
    cpa16(sBd + 16, Bg + 4);
    CP_COMMIT();

    const int nk = K >> 4;
    for (int kt = 0; kt < nk; kt++) {
        const int s = kt & 1;
        if (kt + 1 < nk) {
            const float* Agn = Ag + (kt + 1) * 16;
            const float* Bgn = Bg + (kt + 1) * 16;
            uint32_t da = sAd + (s ^ 1) * stg;
            uint32_t db = sBd + (s ^ 1) * stg;
            cpa16(da,      Agn);
            cpa16(da + 16, Agn + 4);
            cpa16(db,      Bgn);
            cpa16(db + 16, Bgn + 4);
            CP_COMMIT();
            CP_WAIT1();
        } else {
            CP_WAIT0();
        }
        __syncthreads();
#pragma unroll
        for (int ks = 0; ks < 16; ks += 8) {
            unsigned af[4][4], bf[4][2];
#pragma unroll
            for (int mi = 0; mi < 4; mi++) {
                const float* p = &As[s][wm + mi * 16 + gid][ks + cid];
                af[mi][0] = f2tf(p[0]);
                af[mi][1] = f2tf(p[8 * 20]);
                af[mi][2] = f2tf(p[4]);
                af[mi][3] = f2tf(p[8 * 20 + 4]);
            }
#pragma unroll
            for (int ni = 0; ni < 4; ni++) {
                const float* p = &Bs[s][wn + ni * 8 + gid][ks + cid];
                bf[ni][0] = f2tf(p[0]);
                bf[ni][1] = f2tf(p[4]);
            }
#pragma unroll
            for (int mi = 0; mi < 4; mi++)
#pragma unroll
                for (int ni = 0; ni < 4; ni++)
                    mma8(acc[mi][ni], af[mi], bf[ni]);
        }
        __syncthreads();
    }

    // epilogue
#pragma unroll
    for (int mi = 0; mi < 4; mi++) {
        int r0 = bm + wm + mi * 16 + gid;
#pragma unroll
        for (int ni = 0; ni < 4; ni++) {
            int c0 = bn + wn + ni * 8 + 2 * cid;
            float v00 = acc[mi][ni][0], v01 = acc[mi][ni][1];
            float v10 = acc[mi][ni][2], v11 = acc[mi][ni][3];
            if (bias) {
                float b0v = bias[c0], b1v = bias[c0 + 1];
                v00 += b0v; v01 += b1v; v10 += b0v; v11 += b1v;
            }
            if (resid) {
                const float* rr0 = resid + (size_t)r0 * N + c0;
                const float* rr1 = resid + (size_t)(r0 + 8) * N + c0;
                v00 += rr0[0]; v01 += rr0[1]; v10 += rr1[0]; v11 += rr1[1];
            }
            if (dogelu) {
                v00 = 0.5f * v00 * (1.0f + erff(v00 * 0.70710678118654752f));
                v01 = 0.5f * v01 * (1.0f + erff(v01 * 0.70710678118654752f));
                v10 = 0.5f * v10 * (1.0f + erff(v10 * 0.70710678118654752f));
                v11 = 0.5f * v11 * (1.0f + erff(v11 * 0.70710678118654752f));
            }
            *(float2*)&C[(size_t)r0 * N + c0]       = make_float2(v00, v01);
            *(float2*)&C[(size_t)(r0 + 8) * N + c0] = make_float2(v10, v11);
        }
    }
}

// ---------------- attention scores: S = Q K^T * scale + box-mask ------------
__global__ __launch_bounds__(256)
void k_scores(const float* __restrict__ qkv) {
    const int bh = blockIdx.z;
    const int b = bh / H_, h = bh % H_;
    const int i0 = blockIdx.y * 64, j0 = blockIdx.x * 64;
    const int t = threadIdx.x;
    const int tm = (t >> 4) * 4, tn = (t & 15) * 4;
    const size_t sbase = ((size_t)bh * L_ + i0) * L_ + j0;

    if (j0 > i0 + 63) { // fully above the diagonal: all masked
#pragma unroll
        for (int i = 0; i < 4; i++)
#pragma unroll
            for (int j = 0; j < 4; j++)
                g_sc[sbase + (size_t)(tm + i) * L_ + tn + j] = -1e30f;
        return;
    }

    __shared__ float Qs[64][65];
    __shared__ float Ks[64][65];
    const float* qb = qkv + (size_t)(b * L_ + i0) * (3 * D_) + h * HD_;
    const float* kb = qkv + (size_t)(b * L_ + j0) * (3 * D_) + D_ + h * HD_;
    for (int idx = t; idx < 64 * 64; idx += 256) {
        int r = idx >> 6, c = idx & 63;
        Qs[r][c] = qb[(size_t)r * (3 * D_) + c];
        Ks[r][c] = kb[(size_t)r * (3 * D_) + c];
    }
    __syncthreads();

    float acc[4][4] = {};
#pragma unroll 8
    for (int d = 0; d < 64; d++) {
        float q[4], k[4];
#pragma unroll
        for (int i = 0; i < 4; i++) { q[i] = Qs[tm + i][d]; k[i] = Ks[tn + i][d]; }
#pragma unroll
        for (int i = 0; i < 4; i++)
#pragma unroll
            for (int j = 0; j < 4; j++) acc[i][j] += q[i] * k[j];
    }

    const int* segb = g_seg + b * L_;
    const int* gkb  = g_gkey + b * L_;
    const int* vab  = g_valid + b * L_;
#pragma unroll
    for (int i = 0; i < 4; i++) {
        int gi = i0 + tm + i;
        int si = segb[gi];
#pragma unroll
        for (int j = 0; j < 4; j++) {
            int gj = j0 + tn + j;
            float v = acc[i][j] * 0.125f; // 1/sqrt(64)
            bool allowed = (gj <= gi) && vab[gj] &&
                           (segb[gj] == si || gkb[gj] || (gi - gj) <= WIN_);
            g_sc[sbase + (size_t)(tm + i) * L_ + tn + j] = allowed ? v : -1e30f;
        }
    }
}

// ---------------- row softmax over L=1024 -----------------------------------
__global__ __launch_bounds__(256)
void k_softmax() {
    size_t row = blockIdx.x;
    float* p = g_sc + row * L_;
    int t = threadIdx.x;
    float v[4];
    float mx = -1e30f;
#pragma unroll
    for (int i = 0; i < 4; i++) { v[i] = p[i * 256 + t]; mx = fmaxf(mx, v[i]); }
    __shared__ float rmax[8], rsum[8];
#pragma unroll
    for (int o = 16; o > 0; o >>= 1) mx = fmaxf(mx, __shfl_xor_sync(0xffffffffu, mx, o));
    if ((t & 31) == 0) rmax[t >> 5] = mx;
    __syncthreads();
    if (t < 32) {
        float m = (t < 8) ? rmax[t] : -1e30f;
#pragma unroll
        for (int o = 4; o > 0; o >>= 1) m = fmaxf(m, __shfl_xor_sync(0xffffffffu, m, o));
        if (t == 0) rmax[0] = m;
    }
    __syncthreads();
    float bm = rmax[0];
    float s = 0.f;
#pragma unroll
    for (int i = 0; i < 4; i++) { v[i] = __expf(v[i] - bm); s += v[i]; }
#pragma unroll
    for (int o = 16; o > 0; o >>= 1) s += __shfl_xor_sync(0xffffffffu, s, o);
    if ((t & 31) == 0) rsum[t >> 5] = s;
    __syncthreads();
    if (t < 32) {
        float a = (t < 8) ? rsum[t] : 0.f;
#pragma unroll
        for (int o = 4; o > 0; o >>= 1) a += __shfl_xor_sync(0xffffffffu, a, o);
        if (t == 0) rsum[0] = a;
    }
    __syncthreads();
    float inv = 1.0f / rsum[0];
#pragma unroll
    for (int i = 0; i < 4; i++) p[i * 256 + t] = v[i] * inv;
}

// ---------------- y = P @ V --------------------------------------------------
__global__ __launch_bounds__(256)
void k_av(const float* __restrict__ qkv) {
    const int bh = blockIdx.y;
    const int b = bh / H_, h = bh % H_;
    const int i0 = blockIdx.x * 64;
    const int t = threadIdx.x;
    const int tm = (t >> 4) * 4, tn = (t & 15) * 4;
    __shared__ float Ps[64][65];
    __shared__ float Vs[64][65];
    float acc[4][4] = {};
    const float* vb = qkv + (size_t)b * L_ * 3 * D_ + 2 * D_ + h * HD_;
    for (int j0 = 0; j0 <= i0 + 63; j0 += 64) {
        for (int idx = t; idx < 64 * 64; idx += 256) {
            int r = idx >> 6, c = idx & 63;
            Ps[r][c] = g_sc[((size_t)bh * L_ + i0 + r) * L_ + j0 + c];
            Vs[r][c] = vb[(size_t)(j0 + r) * 3 * D_ + c];
        }
        __syncthreads();
#pragma unroll 4
        for (int jj = 0; jj < 64; jj++) {
            float pr[4], vv[4];
#pragma unroll
            for (int i = 0; i < 4; i++) { pr[i] = Ps[tm + i][jj]; vv[i] = Vs[jj][tn + i]; }
#pragma unroll
            for (int i = 0; i < 4; i++)
#pragma unroll
                for (int j = 0; j < 4; j++) acc[i][j] += pr[i] * vv[j];
        }
        __syncthreads();
    }
    float* yb = g_y + (size_t)(b * L_ + i0) * D_ + h * HD_;
#pragma unroll
    for (int i = 0; i < 4; i++)
#pragma unroll
        for (int j = 0; j < 4; j++)
            yb[(size_t)(tm + i) * D_ + tn + j] = acc[i][j];
}

// ---------------- host side --------------------------------------------------
static void gemm(const float* A, const float* Bw, float* C, int M, int N, int K,
                 const float* bias, const float* resid, bool gelu_flag) {
    dim3 grid(N / 128, M / 128);
    k_mma_nt<<<grid, 256>>>(A, Bw, C, M, N, K, bias, resid, gelu_flag ? 1 : 0);
}

extern "C" void kernel_launch(void* const* d_in, const int* in_sizes, int n_in,
                              void* d_out, int out_size) {
    const int*   tokens    = (const int*)d_in[0];
    const int*   types     = (const int*)d_in[1];
    const int*   attn_mask = (const int*)d_in[2];
    const float* tok_emb   = (const float*)d_in[3];
    const float* type_emb  = (const float*)d_in[4];
    const float* pos_emb   = (const float*)d_in[5];
    const float* qkv_w     = (const float*)d_in[6];
    const float* out_w     = (const float*)d_in[7];
    const float* ln1_s     = (const float*)d_in[8];
    const float* ln1_b     = (const float*)d_in[9];
    const float* ln2_s     = (const float*)d_in[10];
    const float* ln2_b     = (const float*)d_in[11];
    const float* ff_w1     = (const float*)d_in[12];
    const float* ff_b1     = (const float*)d_in[13];
    const float* ff_w2     = (const float*)d_in[14];
    const float* ff_b2     = (const float*)d_in[15];
    const float* lnf_s     = (const float*)d_in[16];
    const float* lnf_b     = (const float*)d_in[17];
    const float* head_w    = (const float*)d_in[18];
    float* out = (float*)d_out;

    float *x, *h, *qkv, *y, *ff;
    cudaGetSymbolAddress((void**)&x, g_x);
    cudaGetSymbolAddress((void**)&h, g_h);
    cudaGetSymbolAddress((void**)&qkv, g_qkv);
    cudaGetSymbolAddress((void**)&y, g_y);
    cudaGetSymbolAddress((void**)&ff, g_ff);

    k_embed<<<(M_ * D_ + 255) / 256, 256>>>(tokens, types, tok_emb, type_emb, pos_emb);
    k_maskprep<<<1, 32>>>(tokens, attn_mask);

    for (int l = 0; l < NL_; l++) {
        k_ln<<<M_, 256>>>(x, ln1_s + l * D_, ln1_b + l * D_, h);
        gemm(h, qkv_w + (size_t)l * 3 * D_ * D_, qkv, M_, 3 * D_, D_, nullptr, nullptr, false);
        k_scores<<<dim3(L_ / 64, L_ / 64, B_ * H_), 256>>>(qkv);
        k_softmax<<<B_ * H_ * L_, 256>>>();
        k_av<<<dim3(L_ / 64, B_ * H_), 256>>>(qkv);
        gemm(y, out_w + (size_t)l * D_ * D_, x, M_, D_, D_, nullptr, x, false);
        k_ln<<<M_, 256>>>(x, ln2_s + l * D_, ln2_b + l * D_, h);
        gemm(h, ff_w1 + (size_t)l * FF_ * D_, ff, M_, FF_, D_, ff_b1 + l * FF_, nullptr, true);
        gemm(ff, ff_w2 + (size_t)l * D_ * FF_, x, M_, D_, FF_, ff_b2 + l * D_, x, false);
    }
    k_ln<<<M_, 256>>>(x, lnf_s, lnf_b, h);
    gemm(h, head_w, out, M_, V_, D_, nullptr, nullptr, false);
}

// round 6
// speedup vs baseline: 1.4359x; 1.2542x over previous
#include <cuda_runtime.h>
#include <math.h>
#include <stdint.h>

#define B_ 2
#define L_ 1024
#define D_ 768
#define H_ 12
#define HD_ 64
#define FF_ 3072
#define V_ 32000
#define NL_ 2
#define TOK_BOS 1
#define TOK_SEP 2
#define WIN_ 512
#define EPS_ 1e-5f
#define M_ (B_ * L_) /* 2048 rows */

// ---------------- scratch (static device globals; no allocation) ------------
__device__ float g_x[M_ * D_];
__device__ float g_qkv[M_ * 3 * D_];
__device__ float g_sc[(size_t)B_ * H_ * L_ * L_];   // 100.7 MB
__device__ int   g_seg[B_ * L_];
__device__ int   g_gkey[B_ * L_];
__device__ int   g_valid[B_ * L_];

// fragment-major tf32 operand buffers (uint32 = tf32 bits)
__device__ unsigned g_ht[M_ * D_];        // LN output (A-tiled)
__device__ unsigned g_yt[M_ * D_];        // attention output (A-tiled)
__device__ unsigned g_ft[M_ * FF_];       // FF1 output (A-tiled)
__device__ unsigned g_wqt[NL_ * 3 * D_ * D_];
__device__ unsigned g_wot[NL_ * D_ * D_];
__device__ unsigned g_w1t[NL_ * FF_ * D_];
__device__ unsigned g_w2t[NL_ * D_ * FF_];
__device__ unsigned g_wht[V_ * D_];

// ---------------- helpers ----------------------------------------------------
__device__ __forceinline__ unsigned f2tf(float x) {
    unsigned r;
    asm("cvt.rna.tf32.f32 %0, %1;" : "=r"(r) : "f"(x));
    return r;
}
__device__ __forceinline__ uint32_t smem_u32(const void* p) {
    uint32_t a;
    asm("{ .reg .u64 t; cvta.to.shared.u64 t, %1; cvt.u32.u64 %0, t; }" : "=r"(a) : "l"(p));
    return a;
}
__device__ __forceinline__ void cpa16(uint32_t s, const void* g) {
    asm volatile("cp.async.cg.shared.global [%0], [%1], 16;" :: "r"(s), "l"(g));
}
#define CP_COMMIT() asm volatile("cp.async.commit_group;" ::: "memory")
#define CP_WAIT1()  asm volatile("cp.async.wait_group 1;" ::: "memory")
#define CP_WAIT0()  asm volatile("cp.async.wait_group 0;" ::: "memory")

__device__ __forceinline__ void mma8(float* c, const unsigned* a, const unsigned* b) {
    asm volatile(
        "mma.sync.aligned.m16n8k8.row.col.f32.tf32.tf32.f32 "
        "{%0,%1,%2,%3}, {%4,%5,%6,%7}, {%8,%9}, {%0,%1,%2,%3};\n"
        : "+f"(c[0]), "+f"(c[1]), "+f"(c[2]), "+f"(c[3])
        : "r"(a[0]), "r"(a[1]), "r"(a[2]), "r"(a[3]), "r"(b[0]), "r"(b[1]));
}

// A-tiled (fragment-major) index for element (m, c), inner dim Kd (k8 slabs).
// quad layout per 16-row group & k8 slab: lane = (m&7)*4 + (c&3),
// reg = ((m&15)>>3) + 2*((c&7)>>2). 1024 uints per (128row x 8k) slab.
__device__ __forceinline__ size_t a_idx(int Kd, int m, int c) {
    return ((size_t)(m >> 7) * (Kd >> 3) + (c >> 3)) * 1024
         + (size_t)(((m & 127) >> 4) * 128)
         + (((m & 7) * 4 + (c & 3)) << 2)
         + ((m & 15) >> 3) + 2 * ((c & 7) >> 2);
}
// B-tiled: pairs of n8 tiles. lane = (n&7)*4 + (k&3),
// reg = ((k&7)>>2) + 2*((n&15)>>3). pair = (n&127)>>4.
__device__ __forceinline__ size_t b_idx(int Kd, int n, int k) {
    return ((size_t)(n >> 7) * (Kd >> 3) + (k >> 3)) * 1024
         + (size_t)(((n & 127) >> 4) * 128)
         + (((n & 7) * 4 + (k & 3)) << 2)
         + ((k & 7) >> 2) + 2 * ((n & 15) >> 3);
}

// ---------------- embedding -------------------------------------------------
__global__ void k_embed(const int* __restrict__ tokens, const int* __restrict__ types,
                        const float* __restrict__ tok_emb, const float* __restrict__ type_emb,
                        const float* __restrict__ pos_emb) {
    int idx = blockIdx.x * blockDim.x + threadIdx.x;
    if (idx >= M_ * D_) return;
    int d = idx % D_;
    int bl = idx / D_;
    int l = bl % L_;
    g_x[idx] = tok_emb[(size_t)tokens[bl] * D_ + d]
             + type_emb[(size_t)types[bl] * D_ + d]
             + pos_emb[(size_t)l * D_ + d];
}

// ---------------- mask metadata ----------------------------------------------
__global__ void k_maskprep(const int* __restrict__ tokens, const int* __restrict__ attn_mask) {
    int b = threadIdx.x;
    if (b >= B_) return;
    int seg = 0;
    for (int l = 0; l < L_; l++) {
        int i = b * L_ + l;
        int va = attn_mask[i] != 0;
        int tok = tokens[i];
        int is_sep = (tok == TOK_SEP) && va;
        seg += is_sep;
        g_seg[i] = seg;
        g_gkey[i] = (((tok == TOK_BOS) && va) || is_sep) ? 1 : 0;
        g_valid[i] = va;
    }
}

// ---------------- weight conversion: fp32 [N,K] -> B-tiled tf32 -------------
__global__ void k_cvt_w(const float* __restrict__ W, unsigned* __restrict__ out,
                        int N, int K) {
    int idx = blockIdx.x * blockDim.x + threadIdx.x;
    if (idx >= N * K) return;
    int n = idx / K, k = idx % K;
    out[b_idx(K, n, k)] = f2tf(W[idx]);
}

// ---------------- layernorm -> A-tiled tf32 ----------------------------------
__global__ __launch_bounds__(256)
void k_ln_t(const float* __restrict__ x, const float* __restrict__ sc,
            const float* __restrict__ bi, unsigned* __restrict__ out) {
    int row = blockIdx.x;
    const float* xr = x + (size_t)row * D_;
    int t = threadIdx.x;
    float v0 = xr[t], v1 = xr[t + 256], v2 = xr[t + 512];
    float s = v0 + v1 + v2;
    float ss = v0 * v0 + v1 * v1 + v2 * v2;
    __shared__ float rs[8], rq[8];
#pragma unroll
    for (int o = 16; o > 0; o >>= 1) {
        s  += __shfl_xor_sync(0xffffffffu, s, o);
        ss += __shfl_xor_sync(0xffffffffu, ss, o);
    }
    if ((t & 31) == 0) { rs[t >> 5] = s; rq[t >> 5] = ss; }
    __syncthreads();
    if (t < 32) {
        float a = (t < 8) ? rs[t] : 0.f;
        float q = (t < 8) ? rq[t] : 0.f;
#pragma unroll
        for (int o = 4; o > 0; o >>= 1) {
            a += __shfl_xor_sync(0xffffffffu, a, o);
            q += __shfl_xor_sync(0xffffffffu, q, o);
        }
        if (t == 0) { rs[0] = a; rq[0] = q; }
    }
    __syncthreads();
    float mean = rs[0] * (1.0f / D_);
    float var  = rq[0] * (1.0f / D_) - mean * mean;
    float inv = rsqrtf(var + EPS_);
    out[a_idx(D_, row, t)]       = f2tf((v0 - mean) * inv * sc[t]       + bi[t]);
    out[a_idx(D_, row, t + 256)] = f2tf((v1 - mean) * inv * sc[t + 256] + bi[t + 256]);
    out[a_idx(D_, row, t + 512)] = f2tf((v2 - mean) * inv * sc[t + 512] + bi[t + 512]);
}

// ---------------- TF32 MMA GEMM on fragment-major operands -------------------
// C[M,N] = A @ B^T. 128x128 tile, BK=16, 8 warps (2M x 4N), warp 64x32.
// smem stage = [A k8=0 |A k8=1 |B k8=0 |B k8=1] each 4KB. 2 stages.
template <int DOGELU, int OUTT>
__global__ void __launch_bounds__(256, 2)
k_mma_t(const unsigned* __restrict__ At, const unsigned* __restrict__ Bt,
        float* __restrict__ C, unsigned* __restrict__ Ct,
        int N, int K, int KtOut,
        const float* __restrict__ bias, const float* __restrict__ resid) {
    __shared__ uint4 sm[2][1024];
    const int bm = blockIdx.y * 128, bn = blockIdx.x * 128;
    const int tid = threadIdx.x;
    const int lane = tid & 31, warp = tid >> 5;
    const int wm = (warp & 1) * 64, wn = (warp >> 1) * 32;
    const int gid = lane >> 2, cid = lane & 3;
    const int K8 = K >> 3;

    const uint4* gA = (const uint4*)(At + ((size_t)blockIdx.y * K8) * 1024);
    const uint4* gB = (const uint4*)(Bt + ((size_t)blockIdx.x * K8) * 1024);
    const uint32_t s0 = smem_u32(&sm[0][0]);
    const uint32_t sAld = s0 + tid * 16;           // A: 512 uint4 per kt
    const uint32_t sBld = s0 + 8192 + tid * 16;    // B: 512 uint4 per kt

    float acc[4][4][4];
#pragma unroll
    for (int i = 0; i < 4; i++)
#pragma unroll
        for (int j = 0; j < 4; j++)
#pragma unroll
            for (int r = 0; r < 4; r++) acc[i][j][r] = 0.f;

    // prologue
    cpa16(sAld,        gA + tid);
    cpa16(sAld + 4096, gA + 256 + tid);
    cpa16(sBld,        gB + tid);
    cpa16(sBld + 4096, gB + 256 + tid);
    CP_COMMIT();

    const int nk = K >> 4;
    for (int kt = 0; kt < nk; kt++) {
        const int s = kt & 1;
        if (kt + 1 < nk) {
            const uint4* gAn = gA + (kt + 1) * 512;
            const uint4* gBn = gB + (kt + 1) * 512;
            uint32_t off = (s ^ 1) * 16384;
            cpa16(sAld + off,        gAn + tid);
            cpa16(sAld + off + 4096, gAn + 256 + tid);
            cpa16(sBld + off,        gBn + tid);
            cpa16(sBld + off + 4096, gBn + 256 + tid);
            CP_COMMIT();
            CP_WAIT1();
        } else {
            CP_WAIT0();
        }
        __syncthreads();
        const uint4* sa = &sm[s][0];
        const uint4* sb = &sm[s][512];
#pragma unroll
        for (int ks = 0; ks < 2; ks++) {
            uint4 af[4];
#pragma unroll
            for (int mi = 0; mi < 4; mi++)
                af[mi] = sa[(ks * 8 + (wm >> 4) + mi) * 32 + lane];
            uint4 bq[2];
#pragma unroll
            for (int nt = 0; nt < 2; nt++)
                bq[nt] = sb[(ks * 8 + (wn >> 4) + nt) * 32 + lane];
            unsigned bf[4][2] = {
                {bq[0].x, bq[0].y}, {bq[0].z, bq[0].w},
                {bq[1].x, bq[1].y}, {bq[1].z, bq[1].w}};
#pragma unroll
            for (int mi = 0; mi < 4; mi++)
#pragma unroll
                for (int ni = 0; ni < 4; ni++)
                    mma8(acc[mi][ni], (const unsigned*)&af[mi], bf[ni]);
        }
        __syncthreads();
    }

    // epilogue
#pragma unroll
    for (int mi = 0; mi < 4; mi++) {
        int r0 = bm + wm + mi * 16 + gid;
#pragma unroll
        for (int ni = 0; ni < 4; ni++) {
            int c0 = bn + wn + ni * 8 + 2 * cid;
            float v00 = acc[mi][ni][0], v01 = acc[mi][ni][1];
            float v10 = acc[mi][ni][2], v11 = acc[mi][ni][3];
            if (bias) {
                float b0v = bias[c0], b1v = bias[c0 + 1];
                v00 += b0v; v01 += b1v; v10 += b0v; v11 += b1v;
            }
            if (resid) {
                const float* rr0 = resid + (size_t)r0 * N + c0;
                const float* rr1 = resid + (size_t)(r0 + 8) * N + c0;
                v00 += rr0[0]; v01 += rr0[1]; v10 += rr1[0]; v11 += rr1[1];
            }
            if (DOGELU) {
                v00 = 0.5f * v00 * (1.0f + erff(v00 * 0.70710678118654752f));
                v01 = 0.5f * v01 * (1.0f + erff(v01 * 0.70710678118654752f));
                v10 = 0.5f * v10 * (1.0f + erff(v10 * 0.70710678118654752f));
                v11 = 0.5f * v11 * (1.0f + erff(v11 * 0.70710678118654752f));
            }
            if (OUTT == 0) {
                *(float2*)&C[(size_t)r0 * N + c0]       = make_float2(v00, v01);
                *(float2*)&C[(size_t)(r0 + 8) * N + c0] = make_float2(v10, v11);
            } else {
                Ct[a_idx(KtOut, r0, c0)]         = f2tf(v00);
                Ct[a_idx(KtOut, r0, c0 + 1)]     = f2tf(v01);
                Ct[a_idx(KtOut, r0 + 8, c0)]     = f2tf(v10);
                Ct[a_idx(KtOut, r0 + 8, c0 + 1)] = f2tf(v11);
            }
        }
    }
}

// ---------------- attention scores: S = Q K^T * scale + box-mask ------------
__global__ __launch_bounds__(256)
void k_scores(const float* __restrict__ qkv) {
    const int bh = blockIdx.z;
    const int b = bh / H_, h = bh % H_;
    const int i0 = blockIdx.y * 64, j0 = blockIdx.x * 64;
    const int t = threadIdx.x;
    const int tm = (t >> 4) * 4, tn = (t & 15) * 4;
    const size_t sbase = ((size_t)bh * L_ + i0) * L_ + j0;

    if (j0 > i0 + 63) {
#pragma unroll
        for (int i = 0; i < 4; i++)
#pragma unroll
            for (int j = 0; j < 4; j++)
                g_sc[sbase + (size_t)(tm + i) * L_ + tn + j] = -1e30f;
        return;
    }

    __shared__ float Qs[64][65];
    __shared__ float Ks[64][65];
    const float* qb = qkv + (size_t)(b * L_ + i0) * (3 * D_) + h * HD_;
    const float* kb = qkv + (size_t)(b * L_ + j0) * (3 * D_) + D_ + h * HD_;
    for (int idx = t; idx < 64 * 64; idx += 256) {
        int r = idx >> 6, c = idx & 63;
        Qs[r][c] = qb[(size_t)r * (3 * D_) + c];
        Ks[r][c] = kb[(size_t)r * (3 * D_) + c];
    }
    __syncthreads();

    float acc[4][4] = {};
#pragma unroll 8
    for (int d = 0; d < 64; d++) {
        float q[4], k[4];
#pragma unroll
        for (int i = 0; i < 4; i++) { q[i] = Qs[tm + i][d]; k[i] = Ks[tn + i][d]; }
#pragma unroll
        for (int i = 0; i < 4; i++)
#pragma unroll
            for (int j = 0; j < 4; j++) acc[i][j] += q[i] * k[j];
    }

    const int* segb = g_seg + b * L_;
    const int* gkb  = g_gkey + b * L_;
    const int* vab  = g_valid + b * L_;
#pragma unroll
    for (int i = 0; i < 4; i++) {
        int gi = i0 + tm + i;
        int si = segb[gi];
#pragma unroll
        for (int j = 0; j < 4; j++) {
            int gj = j0 + tn + j;
            float v = acc[i][j] * 0.125f;
            bool allowed = (gj <= gi) && vab[gj] &&
                           (segb[gj] == si || gkb[gj] || (gi - gj) <= WIN_);
            g_sc[sbase + (size_t)(tm + i) * L_ + tn + j] = allowed ? v : -1e30f;
        }
    }
}

// ---------------- row softmax over L=1024 -----------------------------------
__global__ __launch_bounds__(256)
void k_softmax() {
    size_t row = blockIdx.x;
    float* p = g_sc + row * L_;
    int t = threadIdx.x;
    float v[4];
    float mx = -1e30f;
#pragma unroll
    for (int i = 0; i < 4; i++) { v[i] = p[i * 256 + t]; mx = fmaxf(mx, v[i]); }
    __shared__ float rmax[8], rsum[8];
#pragma unroll
    for (int o = 16; o > 0; o >>= 1) mx = fmaxf(mx, __shfl_xor_sync(0xffffffffu, mx, o));
    if ((t & 31) == 0) rmax[t >> 5] = mx;
    __syncthreads();
    if (t < 32) {
        float m = (t < 8) ? rmax[t] : -1e30f;
#pragma unroll
        for (int o = 4; o > 0; o >>= 1) m = fmaxf(m, __shfl_xor_sync(0xffffffffu, m, o));
        if (t == 0) rmax[0] = m;
    }
    __syncthreads();
    float bm = rmax[0];
    float s = 0.f;
#pragma unroll
    for (int i = 0; i < 4; i++) { v[i] = __expf(v[i] - bm); s += v[i]; }
#pragma unroll
    for (int o = 16; o > 0; o >>= 1) s += __shfl_xor_sync(0xffffffffu, s, o);
    if ((t & 31) == 0) rsum[t >> 5] = s;
    __syncthreads();
    if (t < 32) {
        float a = (t < 8) ? rsum[t] : 0.f;
#pragma unroll
        for (int o = 4; o > 0; o >>= 1) a += __shfl_xor_sync(0xffffffffu, a, o);
        if (t == 0) rsum[0] = a;
    }
    __syncthreads();
    float inv = 1.0f / rsum[0];
#pragma unroll
    for (int i = 0; i < 4; i++) p[i * 256 + t] = v[i] * inv;
}

// ---------------- y = P @ V (writes A-tiled tf32) ----------------------------
__global__ __launch_bounds__(256)
void k_av(const float* __restrict__ qkv) {
    const int bh = blockIdx.y;
    const int b = bh / H_, h = bh % H_;
    const int i0 = blockIdx.x * 64;
    const int t = threadIdx.x;
    const int tm = (t >> 4) * 4, tn = (t & 15) * 4;
    __shared__ float Ps[64][65];
    __shared__ float Vs[64][65];
    float acc[4][4] = {};
    const float* vb = qkv + (size_t)b * L_ * 3 * D_ + 2 * D_ + h * HD_;
    for (int j0 = 0; j0 <= i0 + 63; j0 += 64) {
        for (int idx = t; idx < 64 * 64; idx += 256) {
            int r = idx >> 6, c = idx & 63;
            Ps[r][c] = g_sc[((size_t)bh * L_ + i0 + r) * L_ + j0 + c];
            Vs[r][c] = vb[(size_t)(j0 + r) * 3 * D_ + c];
        }
        __syncthreads();
#pragma unroll 4
        for (int jj = 0; jj < 64; jj++) {
            float pr[4], vv[4];
#pragma unroll
            for (int i = 0; i < 4; i++) { pr[i] = Ps[tm + i][jj]; vv[i] = Vs[jj][tn + i]; }
#pragma unroll
            for (int i = 0; i < 4; i++)
#pragma unroll
                for (int j = 0; j < 4; j++) acc[i][j] += pr[i] * vv[j];
        }
        __syncthreads();
    }
#pragma unroll
    for (int i = 0; i < 4; i++) {
        int m = b * L_ + i0 + tm + i;
#pragma unroll
        for (int j = 0; j < 4; j++)
            g_yt[a_idx(D_, m, h * HD_ + tn + j)] = f2tf(acc[i][j]);
    }
}

// ---------------- host side --------------------------------------------------
static void gemm_t(const unsigned* At, const unsigned* Bt, float* C, unsigned* Ct,
                   int N, int K, int ktout, const float* bias, const float* resid,
                   bool gelu_tiled) {
    dim3 grid(N / 128, M_ / 128);
    if (gelu_tiled)
        k_mma_t<1, 1><<<grid, 256>>>(At, Bt, C, Ct, N, K, ktout, bias, resid);
    else
        k_mma_t<0, 0><<<grid, 256>>>(At, Bt, C, Ct, N, K, ktout, bias, resid);
}

extern "C" void kernel_launch(void* const* d_in, const int* in_sizes, int n_in,
                              void* d_out, int out_size) {
    const int*   tokens    = (const int*)d_in[0];
    const int*   types     = (const int*)d_in[1];
    const int*   attn_mask = (const int*)d_in[2];
    const float* tok_emb   = (const float*)d_in[3];
    const float* type_emb  = (const float*)d_in[4];
    const float* pos_emb   = (const float*)d_in[5];
    const float* qkv_w     = (const float*)d_in[6];
    const float* out_w     = (const float*)d_in[7];
    const float* ln1_s     = (const float*)d_in[8];
    const float* ln1_b     = (const float*)d_in[9];
    const float* ln2_s     = (const float*)d_in[10];
    const float* ln2_b     = (const float*)d_in[11];
    const float* ff_w1     = (const float*)d_in[12];
    const float* ff_b1     = (const float*)d_in[13];
    const float* ff_w2     = (const float*)d_in[14];
    const float* ff_b2     = (const float*)d_in[15];
    const float* lnf_s     = (const float*)d_in[16];
    const float* lnf_b     = (const float*)d_in[17];
    const float* head_w    = (const float*)d_in[18];
    float* out = (float*)d_out;

    float *x, *qkv;
    unsigned *ht, *yt, *ft, *wqt, *wot, *w1t, *w2t, *wht;
    cudaGetSymbolAddress((void**)&x, g_x);
    cudaGetSymbolAddress((void**)&qkv, g_qkv);
    cudaGetSymbolAddress((void**)&ht, g_ht);
    cudaGetSymbolAddress((void**)&yt, g_yt);
    cudaGetSymbolAddress((void**)&ft, g_ft);
    cudaGetSymbolAddress((void**)&wqt, g_wqt);
    cudaGetSymbolAddress((void**)&wot, g_wot);
    cudaGetSymbolAddress((void**)&w1t, g_w1t);
    cudaGetSymbolAddress((void**)&w2t, g_w2t);
    cudaGetSymbolAddress((void**)&wht, g_wht);

    // weight conversions (B-tiled tf32); per-layer slices tiled independently
    for (int l = 0; l < NL_; l++) {
        k_cvt_w<<<(3 * D_ * D_ + 255) / 256, 256>>>(qkv_w + (size_t)l * 3 * D_ * D_,
                                                    wqt + (size_t)l * 3 * D_ * D_, 3 * D_, D_);
        k_cvt_w<<<(D_ * D_ + 255) / 256, 256>>>(out_w + (size_t)l * D_ * D_,
                                                wot + (size_t)l * D_ * D_, D_, D_);
        k_cvt_w<<<(FF_ * D_ + 255) / 256, 256>>>(ff_w1 + (size_t)l * FF_ * D_,
                                                 w1t + (size_t)l * FF_ * D_, FF_, D_);
        k_cvt_w<<<(D_ * FF_ + 255) / 256, 256>>>(ff_w2 + (size_t)l * D_ * FF_,
                                                 w2t + (size_t)l * D_ * FF_, D_, FF_);
    }
    k_cvt_w<<<(V_ * D_ + 255) / 256, 256>>>(head_w, wht, V_, D_);

    k_embed<<<(M_ * D_ + 255) / 256, 256>>>(tokens, types, tok_emb, type_emb, pos_emb);
    k_maskprep<<<1, 32>>>(tokens, attn_mask);

    for (int l = 0; l < NL_; l++) {
        size_t wq_off = (size_t)l * 3 * D_ * D_;
        size_t wo_off = (size_t)l * D_ * D_;
        size_t w1_off = (size_t)l * FF_ * D_;
        size_t w2_off = (size_t)l * D_ * FF_;

        k_ln_t<<<M_, 256>>>(x, ln1_s + l * D_, ln1_b + l * D_, ht);
        gemm_t(ht, wqt + wq_off, qkv, nullptr, 3 * D_, D_, 0, nullptr, nullptr, false);
        k_scores<<<dim3(L_ / 64, L_ / 64, B_ * H_), 256>>>(qkv);
        k_softmax<<<B_ * H_ * L_, 256>>>();
        k_av<<<dim3(L_ / 64, B_ * H_), 256>>>(qkv);
        gemm_t(yt, wot + wo_off, x, nullptr, D_, D_, 0, nullptr, x, false);
        k_ln_t<<<M_, 256>>>(x, ln2_s + l * D_, ln2_b + l * D_, ht);
        gemm_t(ht, w1t + w1_off, nullptr, ft, FF_, D_, FF_, ff_b1 + l * FF_, nullptr, true);
        gemm_t(ft, w2t + w2_off, x, nullptr, D_, FF_, 0, ff_b2 + l * D_, x, false);
    }
    k_ln_t<<<M_, 256>>>(x, lnf_s, lnf_b, ht);
    gemm_t(ht, wht, out, nullptr, V_, D_, 0, nullptr, nullptr, false);
}

// round 7
// speedup vs baseline: 1.6175x; 1.1264x over previous
#include <cuda_runtime.h>
#include <math.h>
#include <stdint.h>

#define B_ 2
#define L_ 1024
#define D_ 768
#define H_ 12
#define HD_ 64
#define FF_ 3072
#define V_ 32000
#define NL_ 2
#define TOK_BOS 1
#define TOK_SEP 2
#define WIN_ 512
#define EPS_ 1e-5f
#define M_ (B_ * L_) /* 2048 rows */

// ---------------- scratch (static device globals; no allocation) ------------
__device__ float g_x[M_ * D_];
__device__ float g_qkv[M_ * 3 * D_];
__device__ int   g_seg[B_ * L_];
__device__ int   g_gkey[B_ * L_];
__device__ int   g_valid[B_ * L_];

// fragment-major tf32 operand buffers (uint32 = tf32 bits)
__device__ unsigned g_ht[M_ * D_];
__device__ unsigned g_yt[M_ * D_];
__device__ unsigned g_ft[M_ * FF_];
__device__ unsigned g_wqt[NL_ * 3 * D_ * D_];
__device__ unsigned g_wot[NL_ * D_ * D_];
__device__ unsigned g_w1t[NL_ * FF_ * D_];
__device__ unsigned g_w2t[NL_ * D_ * FF_];
__device__ unsigned g_wht[V_ * D_];

// ---------------- helpers ----------------------------------------------------
__device__ __forceinline__ unsigned f2tf(float x) {
    unsigned r;
    asm("cvt.rna.tf32.f32 %0, %1;" : "=r"(r) : "f"(x));
    return r;
}
__device__ __forceinline__ uint32_t smem_u32(const void* p) {
    uint32_t a;
    asm("{ .reg .u64 t; cvta.to.shared.u64 t, %1; cvt.u32.u64 %0, t; }" : "=r"(a) : "l"(p));
    return a;
}
__device__ __forceinline__ void cpa16(uint32_t s, const void* g) {
    asm volatile("cp.async.cg.shared.global [%0], [%1], 16;" :: "r"(s), "l"(g));
}
#define CP_COMMIT() asm volatile("cp.async.commit_group;" ::: "memory")
#define CP_WAIT1()  asm volatile("cp.async.wait_group 1;" ::: "memory")
#define CP_WAIT0()  asm volatile("cp.async.wait_group 0;" ::: "memory")

__device__ __forceinline__ void mma8(float* c, const unsigned* a, const unsigned* b) {
    asm volatile(
        "mma.sync.aligned.m16n8k8.row.col.f32.tf32.tf32.f32 "
        "{%0,%1,%2,%3}, {%4,%5,%6,%7}, {%8,%9}, {%0,%1,%2,%3};\n"
        : "+f"(c[0]), "+f"(c[1]), "+f"(c[2]), "+f"(c[3])
        : "r"(a[0]), "r"(a[1]), "r"(a[2]), "r"(a[3]), "r"(b[0]), "r"(b[1]));
}

// fragment-major indices (see R6): 1024 uints per (128row x 8k) slab
__device__ __forceinline__ size_t a_idx(int Kd, int m, int c) {
    return ((size_t)(m >> 7) * (Kd >> 3) + (c >> 3)) * 1024
         + (size_t)(((m & 127) >> 4) * 128)
         + (((m & 7) * 4 + (c & 3)) << 2)
         + ((m & 15) >> 3) + 2 * ((c & 7) >> 2);
}
__device__ __forceinline__ size_t b_idx(int Kd, int n, int k) {
    return ((size_t)(n >> 7) * (Kd >> 3) + (k >> 3)) * 1024
         + (size_t)(((n & 127) >> 4) * 128)
         + (((n & 7) * 4 + (k & 3)) << 2)
         + ((k & 7) >> 2) + 2 * ((n & 15) >> 3);
}

// ---------------- embedding -------------------------------------------------
__global__ void k_embed(const int* __restrict__ tokens, const int* __restrict__ types,
                        const float* __restrict__ tok_emb, const float* __restrict__ type_emb,
                        const float* __restrict__ pos_emb) {
    int idx = blockIdx.x * blockDim.x + threadIdx.x;
    if (idx >= M_ * D_) return;
    int d = idx % D_;
    int bl = idx / D_;
    int l = bl % L_;
    g_x[idx] = tok_emb[(size_t)tokens[bl] * D_ + d]
             + type_emb[(size_t)types[bl] * D_ + d]
             + pos_emb[(size_t)l * D_ + d];
}

// ---------------- mask metadata ----------------------------------------------
__global__ void k_maskprep(const int* __restrict__ tokens, const int* __restrict__ attn_mask) {
    int b = threadIdx.x;
    if (b >= B_) return;
    int seg = 0;
    for (int l = 0; l < L_; l++) {
        int i = b * L_ + l;
        int va = attn_mask[i] != 0;
        int tok = tokens[i];
        int is_sep = (tok == TOK_SEP) && va;
        seg += is_sep;
        g_seg[i] = seg;
        g_gkey[i] = (((tok == TOK_BOS) && va) || is_sep) ? 1 : 0;
        g_valid[i] = va;
    }
}

// ---------------- weight conversion: fp32 [N,K] -> B-tiled tf32 -------------
__global__ void k_cvt_w(const float* __restrict__ W, unsigned* __restrict__ out,
                        int N, int K) {
    int idx = blockIdx.x * blockDim.x + threadIdx.x;
    if (idx >= N * K) return;
    int n = idx / K, k = idx % K;
    out[b_idx(K, n, k)] = f2tf(W[idx]);
}

// ---------------- layernorm -> A-tiled tf32 ----------------------------------
__global__ __launch_bounds__(256)
void k_ln_t(const float* __restrict__ x, const float* __restrict__ sc,
            const float* __restrict__ bi, unsigned* __restrict__ out) {
    int row = blockIdx.x;
    const float* xr = x + (size_t)row * D_;
    int t = threadIdx.x;
    float v0 = xr[t], v1 = xr[t + 256], v2 = xr[t + 512];
    float s = v0 + v1 + v2;
    float ss = v0 * v0 + v1 * v1 + v2 * v2;
    __shared__ float rs[8], rq[8];
#pragma unroll
    for (int o = 16; o > 0; o >>= 1) {
        s  += __shfl_xor_sync(0xffffffffu, s, o);
        ss += __shfl_xor_sync(0xffffffffu, ss, o);
    }
    if ((t & 31) == 0) { rs[t >> 5] = s; rq[t >> 5] = ss; }
    __syncthreads();
    if (t < 32) {
        float a = (t < 8) ? rs[t] : 0.f;
        float q = (t < 8) ? rq[t] : 0.f;
#pragma unroll
        for (int o = 4; o > 0; o >>= 1) {
            a += __shfl_xor_sync(0xffffffffu, a, o);
            q += __shfl_xor_sync(0xffffffffu, q, o);
        }
        if (t == 0) { rs[0] = a; rq[0] = q; }
    }
    __syncthreads();
    float mean = rs[0] * (1.0f / D_);
    float var  = rq[0] * (1.0f / D_) - mean * mean;
    float inv = rsqrtf(var + EPS_);
    out[a_idx(D_, row, t)]       = f2tf((v0 - mean) * inv * sc[t]       + bi[t]);
    out[a_idx(D_, row, t + 256)] = f2tf((v1 - mean) * inv * sc[t + 256] + bi[t + 256]);
    out[a_idx(D_, row, t + 512)] = f2tf((v2 - mean) * inv * sc[t + 512] + bi[t + 512]);
}

// ---------------- TF32 MMA GEMM, fragment-major, BK=32, 2-stage cp.async ----
template <int DOGELU, int OUTT>
__global__ void __launch_bounds__(256, 2)
k_mma_t(const unsigned* __restrict__ At, const unsigned* __restrict__ Bt,
        float* __restrict__ C, unsigned* __restrict__ Ct,
        int N, int K, int KtOut,
        const float* __restrict__ bias, const float* __restrict__ resid) {
    extern __shared__ uint4 sm4[];   // [2][2048] uint4 = 64KB
    const int bm = blockIdx.y * 128, bn = blockIdx.x * 128;
    const int tid = threadIdx.x;
    const int lane = tid & 31, warp = tid >> 5;
    const int wm = (warp & 1) * 64, wn = (warp >> 1) * 32;
    const int gid = lane >> 2, cid = lane & 3;
    const int K8 = K >> 3;

    const uint4* gA = (const uint4*)(At + ((size_t)blockIdx.y * K8) * 1024);
    const uint4* gB = (const uint4*)(Bt + ((size_t)blockIdx.x * K8) * 1024);
    const uint32_t s0 = smem_u32(&sm4[0]);
    const uint32_t sAld = s0 + tid * 16;
    const uint32_t sBld = s0 + 16384 + tid * 16;

    float acc[4][4][4];
#pragma unroll
    for (int i = 0; i < 4; i++)
#pragma unroll
        for (int j = 0; j < 4; j++)
#pragma unroll
            for (int r = 0; r < 4; r++) acc[i][j][r] = 0.f;

    // prologue: stage 0 (kt32 = 4 k8-slabs: A 1024 uint4, B 1024 uint4)
#pragma unroll
    for (int i = 0; i < 4; i++) {
        cpa16(sAld + i * 4096, gA + i * 256 + tid);
        cpa16(sBld + i * 4096, gB + i * 256 + tid);
    }
    CP_COMMIT();

    const int nk = K >> 5;
    for (int kt = 0; kt < nk; kt++) {
        const int s = kt & 1;
        if (kt + 1 < nk) {
            const uint4* gAn = gA + (kt + 1) * 1024;
            const uint4* gBn = gB + (kt + 1) * 1024;
            uint32_t off = (s ^ 1) * 32768;
#pragma unroll
            for (int i = 0; i < 4; i++) {
                cpa16(sAld + off + i * 4096, gAn + i * 256 + tid);
                cpa16(sBld + off + i * 4096, gBn + i * 256 + tid);
            }
            CP_COMMIT();
            CP_WAIT1();
        } else {
            CP_WAIT0();
        }
        __syncthreads();
        const uint4* sa = &sm4[s * 2048];
        const uint4* sb = sa + 1024;
#pragma unroll
        for (int ks = 0; ks < 4; ks++) {
            uint4 af[4];
#pragma unroll
            for (int mi = 0; mi < 4; mi++)
                af[mi] = sa[ks * 256 + ((wm >> 4) + mi) * 32 + lane];
            uint4 bq[2];
#pragma unroll
            for (int nt = 0; nt < 2; nt++)
                bq[nt] = sb[ks * 256 + ((wn >> 4) + nt) * 32 + lane];
            unsigned bf[4][2] = {
                {bq[0].x, bq[0].y}, {bq[0].z, bq[0].w},
                {bq[1].x, bq[1].y}, {bq[1].z, bq[1].w}};
#pragma unroll
            for (int mi = 0; mi < 4; mi++)
#pragma unroll
                for (int ni = 0; ni < 4; ni++)
                    mma8(acc[mi][ni], (const unsigned*)&af[mi], bf[ni]);
        }
        __syncthreads();
    }

    // epilogue
#pragma unroll
    for (int mi = 0; mi < 4; mi++) {
        int r0 = bm + wm + mi * 16 + gid;
#pragma unroll
        for (int ni = 0; ni < 4; ni++) {
            int c0 = bn + wn + ni * 8 + 2 * cid;
            float v00 = acc[mi][ni][0], v01 = acc[mi][ni][1];
            float v10 = acc[mi][ni][2], v11 = acc[mi][ni][3];
            if (bias) {
                float b0v = bias[c0], b1v = bias[c0 + 1];
                v00 += b0v; v01 += b1v; v10 += b0v; v11 += b1v;
            }
            if (resid) {
                const float* rr0 = resid + (size_t)r0 * N + c0;
                const float* rr1 = resid + (size_t)(r0 + 8) * N + c0;
                v00 += rr0[0]; v01 += rr0[1]; v10 += rr1[0]; v11 += rr1[1];
            }
            if (DOGELU) {
                v00 = 0.5f * v00 * (1.0f + erff(v00 * 0.70710678118654752f));
                v01 = 0.5f * v01 * (1.0f + erff(v01 * 0.70710678118654752f));
                v10 = 0.5f * v10 * (1.0f + erff(v10 * 0.70710678118654752f));
                v11 = 0.5f * v11 * (1.0f + erff(v11 * 0.70710678118654752f));
            }
            if (OUTT == 0) {
                *(float2*)&C[(size_t)r0 * N + c0]       = make_float2(v00, v01);
                *(float2*)&C[(size_t)(r0 + 8) * N + c0] = make_float2(v10, v11);
            } else {
                Ct[a_idx(KtOut, r0, c0)]         = f2tf(v00);
                Ct[a_idx(KtOut, r0, c0 + 1)]     = f2tf(v01);
                Ct[a_idx(KtOut, r0 + 8, c0)]     = f2tf(v10);
                Ct[a_idx(KtOut, r0 + 8, c0 + 1)] = f2tf(v11);
            }
        }
    }
}

// ---------------- fused flash attention (per b,h, 64-query tile) ------------
// online softmax; writes A-tiled tf32 into g_yt. smem: Q(64x65) K(64x65)
// V(64x64) P(64x65) fp32 = 66304 B dynamic.
__global__ __launch_bounds__(256)
void k_attn(const float* __restrict__ qkv) {
    extern __shared__ float sm[];
    float* Qs = sm;                       // stride 65
    float* Ks = sm + 64 * 65;             // stride 65
    float* Vs = sm + 2 * 64 * 65;         // stride 64
    float* Ps = sm + 2 * 64 * 65 + 64 * 64; // stride 65
    __shared__ int sSeg[64], sGk[64], sVa[64];

    const int bh = blockIdx.y;
    const int b = bh / H_, h = bh % H_;
    const int i0 = (gridDim.x - 1 - blockIdx.x) * 64;  // heavy tiles first
    const int t = threadIdx.x;
    const int tm = (t >> 4) * 4, tn = (t & 15) * 4;

    const float* qb = qkv + (size_t)(b * L_ + i0) * (3 * D_) + h * HD_;
    for (int idx = t; idx < 64 * 64; idx += 256) {
        int r = idx >> 6, c = idx & 63;
        Qs[r * 65 + c] = qb[(size_t)r * (3 * D_) + c];
    }
    int gi[4], si[4];
#pragma unroll
    for (int i = 0; i < 4; i++) {
        gi[i] = i0 + tm + i;
        si[i] = g_seg[b * L_ + gi[i]];
    }

    float m[4] = {-1e30f, -1e30f, -1e30f, -1e30f};
    float lsum[4] = {0.f, 0.f, 0.f, 0.f};
    float o[4][4] = {};

    for (int j0 = 0; j0 <= i0; j0 += 64) {
        __syncthreads();   // previous P/V consumption done
        const float* kb = qkv + (size_t)(b * L_ + j0) * (3 * D_) + D_ + h * HD_;
        const float* vb = qkv + (size_t)(b * L_ + j0) * (3 * D_) + 2 * D_ + h * HD_;
        for (int idx = t; idx < 64 * 64; idx += 256) {
            int r = idx >> 6, c = idx & 63;
            Ks[r * 65 + c] = kb[(size_t)r * (3 * D_) + c];
            Vs[r * 64 + c] = vb[(size_t)r * (3 * D_) + c];
        }
        if (t < 64) {
            int gj = b * L_ + j0 + t;
            sSeg[t] = g_seg[gj];
            sGk[t]  = g_gkey[gj];
            sVa[t]  = g_valid[gj];
        }
        __syncthreads();

        // S = Q K^T
        float s[4][4] = {};
#pragma unroll 8
        for (int d = 0; d < 64; d++) {
            float q[4], k[4];
#pragma unroll
            for (int i = 0; i < 4; i++) { q[i] = Qs[(tm + i) * 65 + d]; k[i] = Ks[(tn + i) * 65 + d]; }
#pragma unroll
            for (int i = 0; i < 4; i++)
#pragma unroll
                for (int j = 0; j < 4; j++) s[i][j] += q[i] * k[j];
        }
        // mask + scale
#pragma unroll
        for (int i = 0; i < 4; i++)
#pragma unroll
            for (int j = 0; j < 4; j++) {
                int gj = j0 + tn + j;
                bool allowed = (gj <= gi[i]) && sVa[tn + j] &&
                               (sSeg[tn + j] == si[i] || sGk[tn + j] || (gi[i] - gj) <= WIN_);
                s[i][j] = allowed ? s[i][j] * 0.125f : -1e30f;
            }
        // online softmax update per row
#pragma unroll
        for (int i = 0; i < 4; i++) {
            float rm = fmaxf(fmaxf(s[i][0], s[i][1]), fmaxf(s[i][2], s[i][3]));
#pragma unroll
            for (int off = 8; off > 0; off >>= 1)
                rm = fmaxf(rm, __shfl_xor_sync(0xffffffffu, rm, off));
            float mn = fmaxf(m[i], rm);
            float alpha = __expf(m[i] - mn);
            m[i] = mn;
            float p0 = (s[i][0] > -1e29f) ? __expf(s[i][0] - mn) : 0.f;
            float p1 = (s[i][1] > -1e29f) ? __expf(s[i][1] - mn) : 0.f;
            float p2 = (s[i][2] > -1e29f) ? __expf(s[i][2] - mn) : 0.f;
            float p3 = (s[i][3] > -1e29f) ? __expf(s[i][3] - mn) : 0.f;
            float rsm = p0 + p1 + p2 + p3;
#pragma unroll
            for (int off = 8; off > 0; off >>= 1)
                rsm += __shfl_xor_sync(0xffffffffu, rsm, off);
            lsum[i] = lsum[i] * alpha + rsm;
#pragma unroll
            for (int j = 0; j < 4; j++) o[i][j] *= alpha;
            Ps[(tm + i) * 65 + tn + 0] = p0;
            Ps[(tm + i) * 65 + tn + 1] = p1;
            Ps[(tm + i) * 65 + tn + 2] = p2;
            Ps[(tm + i) * 65 + tn + 3] = p3;
        }
        __syncthreads();
        // O += P @ V
#pragma unroll 4
        for (int jj = 0; jj < 64; jj++) {
            float pr[4], vv[4];
#pragma unroll
            for (int i = 0; i < 4; i++) { pr[i] = Ps[(tm + i) * 65 + jj]; vv[i] = Vs[jj * 64 + tn + i]; }
#pragma unroll
            for (int i = 0; i < 4; i++)
#pragma unroll
                for (int j = 0; j < 4; j++) o[i][j] += pr[i] * vv[j];
        }
    }
#pragma unroll
    for (int i = 0; i < 4; i++) {
        float inv = 1.0f / lsum[i];
        int mrow = b * L_ + gi[i];
#pragma unroll
        for (int j = 0; j < 4; j++)
            g_yt[a_idx(D_, mrow, h * HD_ + tn + j)] = f2tf(o[i][j] * inv);
    }
}

// ---------------- host side --------------------------------------------------
#define GEMM_SMEM_ 65536
#define ATTN_SMEM_ 66304

static void gemm_t(const unsigned* At, const unsigned* Bt, float* C, unsigned* Ct,
                   int N, int K, int ktout, const float* bias, const float* resid,
                   bool gelu_tiled) {
    dim3 grid(N / 128, M_ / 128);
    if (gelu_tiled)
        k_mma_t<1, 1><<<grid, 256, GEMM_SMEM_>>>(At, Bt, C, Ct, N, K, ktout, bias, resid);
    else
        k_mma_t<0, 0><<<grid, 256, GEMM_SMEM_>>>(At, Bt, C, Ct, N, K, ktout, bias, resid);
}

extern "C" void kernel_launch(void* const* d_in, const int* in_sizes, int n_in,
                              void* d_out, int out_size) {
    const int*   tokens    = (const int*)d_in[0];
    const int*   types     = (const int*)d_in[1];
    const int*   attn_mask = (const int*)d_in[2];
    const float* tok_emb   = (const float*)d_in[3];
    const float* type_emb  = (const float*)d_in[4];
    const float* pos_emb   = (const float*)d_in[5];
    const float* qkv_w     = (const float*)d_in[6];
    const float* out_w     = (const float*)d_in[7];
    const float* ln1_s     = (const float*)d_in[8];
    const float* ln1_b     = (const float*)d_in[9];
    const float* ln2_s     = (const float*)d_in[10];
    const float* ln2_b     = (const float*)d_in[11];
    const float* ff_w1     = (const float*)d_in[12];
    const float* ff_b1     = (const float*)d_in[13];
    const float* ff_w2     = (const float*)d_in[14];
    const float* ff_b2     = (const float*)d_in[15];
    const float* lnf_s     = (const float*)d_in[16];
    const float* lnf_b     = (const float*)d_in[17];
    const float* head_w    = (const float*)d_in[18];
    float* out = (float*)d_out;

    cudaFuncSetAttribute(k_mma_t<0, 0>, cudaFuncAttributeMaxDynamicSharedMemorySize, GEMM_SMEM_);
    cudaFuncSetAttribute(k_mma_t<1, 1>, cudaFuncAttributeMaxDynamicSharedMemorySize, GEMM_SMEM_);
    cudaFuncSetAttribute(k_attn, cudaFuncAttributeMaxDynamicSharedMemorySize, ATTN_SMEM_);

    float *x, *qkv;
    unsigned *ht, *yt, *ft, *wqt, *wot, *w1t, *w2t, *wht;
    cudaGetSymbolAddress((void**)&x, g_x);
    cudaGetSymbolAddress((void**)&qkv, g_qkv);
    cudaGetSymbolAddress((void**)&ht, g_ht);
    cudaGetSymbolAddress((void**)&yt, g_yt);
    cudaGetSymbolAddress((void**)&ft, g_ft);
    cudaGetSymbolAddress((void**)&wqt, g_wqt);
    cudaGetSymbolAddress((void**)&wot, g_wot);
    cudaGetSymbolAddress((void**)&w1t, g_w1t);
    cudaGetSymbolAddress((void**)&w2t, g_w2t);
    cudaGetSymbolAddress((void**)&wht, g_wht);

    for (int l = 0; l < NL_; l++) {
        k_cvt_w<<<(3 * D_ * D_ + 255) / 256, 256>>>(qkv_w + (size_t)l * 3 * D_ * D_,
                                                    wqt + (size_t)l * 3 * D_ * D_, 3 * D_, D_);
        k_cvt_w<<<(D_ * D_ + 255) / 256, 256>>>(out_w + (size_t)l * D_ * D_,
                                                wot + (size_t)l * D_ * D_, D_, D_);
        k_cvt_w<<<(FF_ * D_ + 255) / 256, 256>>>(ff_w1 + (size_t)l * FF_ * D_,
                                                 w1t + (size_t)l * FF_ * D_, FF_, D_);
        k_cvt_w<<<(D_ * FF_ + 255) / 256, 256>>>(ff_w2 + (size_t)l * D_ * FF_,
                                                 w2t + (size_t)l * D_ * FF_, D_, FF_);
    }
    k_cvt_w<<<(V_ * D_ + 255) / 256, 256>>>(head_w, wht, V_, D_);

    k_embed<<<(M_ * D_ + 255) / 256, 256>>>(tokens, types, tok_emb, type_emb, pos_emb);
    k_maskprep<<<1, 32>>>(tokens, attn_mask);

    for (int l = 0; l < NL_; l++) {
        size_t wq_off = (size_t)l * 3 * D_ * D_;
        size_t wo_off = (size_t)l * D_ * D_;
        size_t w1_off = (size_t)l * FF_ * D_;
        size_t w2_off = (size_t)l * D_ * FF_;

        k_ln_t<<<M_, 256>>>(x, ln1_s + l * D_, ln1_b + l * D_, ht);
        gemm_t(ht, wqt + wq_off, qkv, nullptr, 3 * D_, D_, 0, nullptr, nullptr, false);
        k_attn<<<dim3(L_ / 64, B_ * H_), 256, ATTN_SMEM_>>>(qkv);
        gemm_t(yt, wot + wo_off, x, nullptr, D_, D_, 0, nullptr, x, false);
        k_ln_t<<<M_, 256>>>(x, ln2_s + l * D_, ln2_b + l * D_, ht);
        gemm_t(ht, w1t + w1_off, nullptr, ft, FF_, D_, FF_, ff_b1 + l * FF_, nullptr, true);
        gemm_t(ft, w2t + w2_off, x, nullptr, D_, FF_, 0, ff_b2 + l * D_, x, false);
    }
    k_ln_t<<<M_, 256>>>(x, lnf_s, lnf_b, ht);
    gemm_t(ht, wht, out, nullptr, V_, D_, 0, nullptr, nullptr, false);
}

// round 8
// speedup vs baseline: 1.6399x; 1.0139x over previous
#include <cuda_runtime.h>
#include <math.h>
#include <stdint.h>

#define B_ 2
#define L_ 1024
#define D_ 768
#define H_ 12
#define HD_ 64
#define FF_ 3072
#define V_ 32000
#define NL_ 2
#define TOK_BOS 1
#define TOK_SEP 2
#define WIN_ 512
#define EPS_ 1e-5f
#define M_ (B_ * L_) /* 2048 rows */

// ---------------- scratch (static device globals; no allocation) ------------
__device__ float g_x[M_ * D_];
__device__ float g_qkv[M_ * 3 * D_];
__device__ int   g_seg[B_ * L_];
__device__ int   g_gkey[B_ * L_];
__device__ int   g_valid[B_ * L_];

// fragment-major tf32 operand buffers (uint32 = tf32 bits)
__device__ unsigned g_ht[M_ * D_];
__device__ unsigned g_yt[M_ * D_];
__device__ unsigned g_ft[M_ * FF_];
__device__ unsigned g_wqt[NL_ * 3 * D_ * D_];
__device__ unsigned g_wot[NL_ * D_ * D_];
__device__ unsigned g_w1t[NL_ * FF_ * D_];
__device__ unsigned g_w2t[NL_ * D_ * FF_];
__device__ unsigned g_wht[V_ * D_];

// ---------------- helpers ----------------------------------------------------
__device__ __forceinline__ unsigned f2tf(float x) {
    unsigned r;
    asm("cvt.rna.tf32.f32 %0, %1;" : "=r"(r) : "f"(x));
    return r;
}
__device__ __forceinline__ uint32_t smem_u32(const void* p) {
    uint32_t a;
    asm("{ .reg .u64 t; cvta.to.shared.u64 t, %1; cvt.u32.u64 %0, t; }" : "=r"(a) : "l"(p));
    return a;
}
__device__ __forceinline__ void cpa16(uint32_t s, const void* g) {
    asm volatile("cp.async.cg.shared.global [%0], [%1], 16;" :: "r"(s), "l"(g));
}
#define CP_COMMIT() asm volatile("cp.async.commit_group;" ::: "memory")
#define CP_WAIT1()  asm volatile("cp.async.wait_group 1;" ::: "memory")
#define CP_WAIT0()  asm volatile("cp.async.wait_group 0;" ::: "memory")

__device__ __forceinline__ void mma8(float* c, const unsigned* a, const unsigned* b) {
    asm volatile(
        "mma.sync.aligned.m16n8k8.row.col.f32.tf32.tf32.f32 "
        "{%0,%1,%2,%3}, {%4,%5,%6,%7}, {%8,%9}, {%0,%1,%2,%3};\n"
        : "+f"(c[0]), "+f"(c[1]), "+f"(c[2]), "+f"(c[3])
        : "r"(a[0]), "r"(a[1]), "r"(a[2]), "r"(a[3]), "r"(b[0]), "r"(b[1]));
}

// fragment-major indices (see R6): 1024 uints per (128row x 8k) slab
__device__ __forceinline__ size_t a_idx(int Kd, int m, int c) {
    return ((size_t)(m >> 7) * (Kd >> 3) + (c >> 3)) * 1024
         + (size_t)(((m & 127) >> 4) * 128)
         + (((m & 7) * 4 + (c & 3)) << 2)
         + ((m & 15) >> 3) + 2 * ((c & 7) >> 2);
}
__device__ __forceinline__ size_t b_idx(int Kd, int n, int k) {
    return ((size_t)(n >> 7) * (Kd >> 3) + (k >> 3)) * 1024
         + (size_t)(((n & 127) >> 4) * 128)
         + (((n & 7) * 4 + (k & 3)) << 2)
         + ((k & 7) >> 2) + 2 * ((n & 15) >> 3);
}

// ---------------- embedding -------------------------------------------------
__global__ void k_embed(const int* __restrict__ tokens, const int* __restrict__ types,
                        const float* __restrict__ tok_emb, const float* __restrict__ type_emb,
                        const float* __restrict__ pos_emb) {
    int idx = blockIdx.x * blockDim.x + threadIdx.x;
    if (idx >= M_ * D_) return;
    int d = idx % D_;
    int bl = idx / D_;
    int l = bl % L_;
    g_x[idx] = tok_emb[(size_t)tokens[bl] * D_ + d]
             + type_emb[(size_t)types[bl] * D_ + d]
             + pos_emb[(size_t)l * D_ + d];
}

// ---------------- mask metadata ----------------------------------------------
__global__ void k_maskprep(const int* __restrict__ tokens, const int* __restrict__ attn_mask) {
    int b = threadIdx.x;
    if (b >= B_) return;
    int seg = 0;
    for (int l = 0; l < L_; l++) {
        int i = b * L_ + l;
        int va = attn_mask[i] != 0;
        int tok = tokens[i];
        int is_sep = (tok == TOK_SEP) && va;
        seg += is_sep;
        g_seg[i] = seg;
        g_gkey[i] = (((tok == TOK_BOS) && va) || is_sep) ? 1 : 0;
        g_valid[i] = va;
    }
}

// ---------------- weight conversion: fp32 [N,K] -> B-tiled tf32 -------------
__global__ void k_cvt_w(const float* __restrict__ W, unsigned* __restrict__ out,
                        int N, int K) {
    int idx = blockIdx.x * blockDim.x + threadIdx.x;
    if (idx >= N * K) return;
    int n = idx / K, k = idx % K;
    out[b_idx(K, n, k)] = f2tf(W[idx]);
}

// ---------------- layernorm -> A-tiled tf32 ----------------------------------
__global__ __launch_bounds__(256)
void k_ln_t(const float* __restrict__ x, const float* __restrict__ sc,
            const float* __restrict__ bi, unsigned* __restrict__ out) {
    int row = blockIdx.x;
    const float* xr = x + (size_t)row * D_;
    int t = threadIdx.x;
    float v0 = xr[t], v1 = xr[t + 256], v2 = xr[t + 512];
    float s = v0 + v1 + v2;
    float ss = v0 * v0 + v1 * v1 + v2 * v2;
    __shared__ float rs[8], rq[8];
#pragma unroll
    for (int o = 16; o > 0; o >>= 1) {
        s  += __shfl_xor_sync(0xffffffffu, s, o);
        ss += __shfl_xor_sync(0xffffffffu, ss, o);
    }
    if ((t & 31) == 0) { rs[t >> 5] = s; rq[t >> 5] = ss; }
    __syncthreads();
    if (t < 32) {
        float a = (t < 8) ? rs[t] : 0.f;
        float q = (t < 8) ? rq[t] : 0.f;
#pragma unroll
        for (int o = 4; o > 0; o >>= 1) {
            a += __shfl_xor_sync(0xffffffffu, a, o);
            q += __shfl_xor_sync(0xffffffffu, q, o);
        }
        if (t == 0) { rs[0] = a; rq[0] = q; }
    }
    __syncthreads();
    float mean = rs[0] * (1.0f / D_);
    float var  = rq[0] * (1.0f / D_) - mean * mean;
    float inv = rsqrtf(var + EPS_);
    out[a_idx(D_, row, t)]       = f2tf((v0 - mean) * inv * sc[t]       + bi[t]);
    out[a_idx(D_, row, t + 256)] = f2tf((v1 - mean) * inv * sc[t + 256] + bi[t + 256]);
    out[a_idx(D_, row, t + 512)] = f2tf((v2 - mean) * inv * sc[t + 512] + bi[t + 512]);
}

// ---------------- TF32 MMA GEMM, fragment-major, BK=32, 3-stage cp.async ----
// grid: x = M/128 (fastest) for B-tile L2 reuse, y = N/128.
template <int DOGELU, int OUTT>
__global__ void __launch_bounds__(256, 2)
k_mma_t(const unsigned* __restrict__ At, const unsigned* __restrict__ Bt,
        float* __restrict__ C, unsigned* __restrict__ Ct,
        int N, int K, int KtOut,
        const float* __restrict__ bias, const float* __restrict__ resid) {
    extern __shared__ uint4 sm4[];   // [3][2048] uint4 = 96KB
    const int bm = blockIdx.x * 128, bn = blockIdx.y * 128;
    const int tid = threadIdx.x;
    const int lane = tid & 31, warp = tid >> 5;
    const int wm = (warp & 1) * 64, wn = (warp >> 1) * 32;
    const int gid = lane >> 2, cid = lane & 3;
    const int K8 = K >> 3;

    const uint4* gA = (const uint4*)(At + ((size_t)blockIdx.x * K8) * 1024);
    const uint4* gB = (const uint4*)(Bt + ((size_t)blockIdx.y * K8) * 1024);
    const uint32_t s0 = smem_u32(&sm4[0]);
    const uint32_t sAld = s0 + tid * 16;
    const uint32_t sBld = s0 + 16384 + tid * 16;

    float acc[4][4][4];
#pragma unroll
    for (int i = 0; i < 4; i++)
#pragma unroll
        for (int j = 0; j < 4; j++)
#pragma unroll
            for (int r = 0; r < 4; r++) acc[i][j][r] = 0.f;

    const int nk = K >> 5;
    // prologue: stages 0, 1
#pragma unroll
    for (int st = 0; st < 2; st++) {
        const uint4* gAn = gA + st * 1024;
        const uint4* gBn = gB + st * 1024;
        uint32_t off = st * 32768;
#pragma unroll
        for (int i = 0; i < 4; i++) {
            cpa16(sAld + off + i * 4096, gAn + i * 256 + tid);
            cpa16(sBld + off + i * 4096, gBn + i * 256 + tid);
        }
        CP_COMMIT();
    }

    int s = 0;
    for (int kt = 0; kt < nk; kt++) {
        if (kt < nk - 1) { CP_WAIT1(); } else { CP_WAIT0(); }
        __syncthreads();   // stage kt visible to all; also WAR for buffer reuse
        if (kt + 2 < nk) {
            const uint4* gAn = gA + (kt + 2) * 1024;
            const uint4* gBn = gB + (kt + 2) * 1024;
            int sn = s + 2; if (sn >= 3) sn -= 3;
            uint32_t off = sn * 32768;
#pragma unroll
            for (int i = 0; i < 4; i++) {
                cpa16(sAld + off + i * 4096, gAn + i * 256 + tid);
                cpa16(sBld + off + i * 4096, gBn + i * 256 + tid);
            }
            CP_COMMIT();
        }
        const uint4* sa = &sm4[s * 2048];
        const uint4* sb = sa + 1024;
#pragma unroll
        for (int ks = 0; ks < 4; ks++) {
            uint4 af[4];
#pragma unroll
            for (int mi = 0; mi < 4; mi++)
                af[mi] = sa[ks * 256 + ((wm >> 4) + mi) * 32 + lane];
            uint4 bq[2];
#pragma unroll
            for (int nt = 0; nt < 2; nt++)
                bq[nt] = sb[ks * 256 + ((wn >> 4) + nt) * 32 + lane];
            unsigned bf[4][2] = {
                {bq[0].x, bq[0].y}, {bq[0].z, bq[0].w},
                {bq[1].x, bq[1].y}, {bq[1].z, bq[1].w}};
#pragma unroll
            for (int mi = 0; mi < 4; mi++)
#pragma unroll
                for (int ni = 0; ni < 4; ni++)
                    mma8(acc[mi][ni], (const unsigned*)&af[mi], bf[ni]);
        }
        if (++s == 3) s = 0;
    }

    // epilogue
#pragma unroll
    for (int mi = 0; mi < 4; mi++) {
        int r0 = bm + wm + mi * 16 + gid;
#pragma unroll
        for (int ni = 0; ni < 4; ni++) {
            int c0 = bn + wn + ni * 8 + 2 * cid;
            float v00 = acc[mi][ni][0], v01 = acc[mi][ni][1];
            float v10 = acc[mi][ni][2], v11 = acc[mi][ni][3];
            if (bias) {
                float b0v = bias[c0], b1v = bias[c0 + 1];
                v00 += b0v; v01 += b1v; v10 += b0v; v11 += b1v;
            }
            if (resid) {
                const float* rr0 = resid + (size_t)r0 * N + c0;
                const float* rr1 = resid + (size_t)(r0 + 8) * N + c0;
                v00 += rr0[0]; v01 += rr0[1]; v10 += rr1[0]; v11 += rr1[1];
            }
            if (DOGELU) {
                v00 = 0.5f * v00 * (1.0f + erff(v00 * 0.70710678118654752f));
                v01 = 0.5f * v01 * (1.0f + erff(v01 * 0.70710678118654752f));
                v10 = 0.5f * v10 * (1.0f + erff(v10 * 0.70710678118654752f));
                v11 = 0.5f * v11 * (1.0f + erff(v11 * 0.70710678118654752f));
            }
            if (OUTT == 0) {
                *(float2*)&C[(size_t)r0 * N + c0]       = make_float2(v00, v01);
                *(float2*)&C[(size_t)(r0 + 8) * N + c0] = make_float2(v10, v11);
            } else {
                Ct[a_idx(KtOut, r0, c0)]         = f2tf(v00);
                Ct[a_idx(KtOut, r0, c0 + 1)]     = f2tf(v01);
                Ct[a_idx(KtOut, r0 + 8, c0)]     = f2tf(v10);
                Ct[a_idx(KtOut, r0 + 8, c0 + 1)] = f2tf(v11);
            }
        }
    }
}

// ---------------- fused flash attention (per b,h, 64-query tile) ------------
__global__ __launch_bounds__(256)
void k_attn(const float* __restrict__ qkv) {
    extern __shared__ float sm[];
    float* Qs = sm;
    float* Ks = sm + 64 * 65;
    float* Vs = sm + 2 * 64 * 65;
    float* Ps = sm + 2 * 64 * 65 + 64 * 64;
    __shared__ int sSeg[64], sGk[64], sVa[64];

    const int bh = blockIdx.y;
    const int b = bh / H_, h = bh % H_;
    const int i0 = (gridDim.x - 1 - blockIdx.x) * 64;
    const int t = threadIdx.x;
    const int tm = (t >> 4) * 4, tn = (t & 15) * 4;

    const float* qb = qkv + (size_t)(b * L_ + i0) * (3 * D_) + h * HD_;
    for (int idx = t; idx < 64 * 64; idx += 256) {
        int r = idx >> 6, c = idx & 63;
        Qs[r * 65 + c] = qb[(size_t)r * (3 * D_) + c];
    }
    int gi[4], si[4];
#pragma unroll
    for (int i = 0; i < 4; i++) {
        gi[i] = i0 + tm + i;
        si[i] = g_seg[b * L_ + gi[i]];
    }

    float m[4] = {-1e30f, -1e30f, -1e30f, -1e30f};
    float lsum[4] = {0.f, 0.f, 0.f, 0.f};
    float o[4][4] = {};

    for (int j0 = 0; j0 <= i0; j0 += 64) {
        __syncthreads();
        const float* kb = qkv + (size_t)(b * L_ + j0) * (3 * D_) + D_ + h * HD_;
        const float* vb = qkv + (size_t)(b * L_ + j0) * (3 * D_) + 2 * D_ + h * HD_;
        for (int idx = t; idx < 64 * 64; idx += 256) {
            int r = idx >> 6, c = idx & 63;
            Ks[r * 65 + c] = kb[(size_t)r * (3 * D_) + c];
            Vs[r * 64 + c] = vb[(size_t)r * (3 * D_) + c];
        }
        if (t < 64) {
            int gj = b * L_ + j0 + t;
            sSeg[t] = g_seg[gj];
            sGk[t]  = g_gkey[gj];
            sVa[t]  = g_valid[gj];
        }
        __syncthreads();

        float s[4][4] = {};
#pragma unroll 8
        for (int d = 0; d < 64; d++) {
            float q[4], k[4];
#pragma unroll
            for (int i = 0; i < 4; i++) { q[i] = Qs[(tm + i) * 65 + d]; k[i] = Ks[(tn + i) * 65 + d]; }
#pragma unroll
            for (int i = 0; i < 4; i++)
#pragma unroll
                for (int j = 0; j < 4; j++) s[i][j] += q[i] * k[j];
        }
#pragma unroll
        for (int i = 0; i < 4; i++)
#pragma unroll
            for (int j = 0; j < 4; j++) {
                int gj = j0 + tn + j;
                bool allowed = (gj <= gi[i]) && sVa[tn + j] &&
                               (sSeg[tn + j] == si[i] || sGk[tn + j] || (gi[i] - gj) <= WIN_);
                s[i][j] = allowed ? s[i][j] * 0.125f : -1e30f;
            }
#pragma unroll
        for (int i = 0; i < 4; i++) {
            float rm = fmaxf(fmaxf(s[i][0], s[i][1]), fmaxf(s[i][2], s[i][3]));
#pragma unroll
            for (int off = 8; off > 0; off >>= 1)
                rm = fmaxf(rm, __shfl_xor_sync(0xffffffffu, rm, off));
            float mn = fmaxf(m[i], rm);
            float alpha = __expf(m[i] - mn);
            m[i] = mn;
            float p0 = (s[i][0] > -1e29f) ? __expf(s[i][0] - mn) : 0.f;
            float p1 = (s[i][1] > -1e29f) ? __expf(s[i][1] - mn) : 0.f;
            float p2 = (s[i][2] > -1e29f) ? __expf(s[i][2] - mn) : 0.f;
            float p3 = (s[i][3] > -1e29f) ? __expf(s[i][3] - mn) : 0.f;
            float rsm = p0 + p1 + p2 + p3;
#pragma unroll
            for (int off = 8; off > 0; off >>= 1)
                rsm += __shfl_xor_sync(0xffffffffu, rsm, off);
            lsum[i] = lsum[i] * alpha + rsm;
#pragma unroll
            for (int j = 0; j < 4; j++) o[i][j] *= alpha;
            Ps[(tm + i) * 65 + tn + 0] = p0;
            Ps[(tm + i) * 65 + tn + 1] = p1;
            Ps[(tm + i) * 65 + tn + 2] = p2;
            Ps[(tm + i) * 65 + tn + 3] = p3;
        }
        __syncthreads();
#pragma unroll 4
        for (int jj = 0; jj < 64; jj++) {
            float pr[4], vv[4];
#pragma unroll
            for (int i = 0; i < 4; i++) { pr[i] = Ps[(tm + i) * 65 + jj]; vv[i] = Vs[jj * 64 + tn + i]; }
#pragma unroll
            for (int i = 0; i < 4; i++)
#pragma unroll
                for (int j = 0; j < 4; j++) o[i][j] += pr[i] * vv[j];
        }
    }
#pragma unroll
    for (int i = 0; i < 4; i++) {
        float inv = 1.0f / lsum[i];
        int mrow = b * L_ + gi[i];
#pragma unroll
        for (int j = 0; j < 4; j++)
            g_yt[a_idx(D_, mrow, h * HD_ + tn + j)] = f2tf(o[i][j] * inv);
    }
}

// ---------------- host side --------------------------------------------------
#define GEMM_SMEM_ 98304
#define ATTN_SMEM_ 66304

static void gemm_t(const unsigned* At, const unsigned* Bt, float* C, unsigned* Ct,
                   int N, int K, int ktout, const float* bias, const float* resid,
                   bool gelu_tiled) {
    dim3 grid(M_ / 128, N / 128);
    if (gelu_tiled)
        k_mma_t<1, 1><<<grid, 256, GEMM_SMEM_>>>(At, Bt, C, Ct, N, K, ktout, bias, resid);
    else
        k_mma_t<0, 0><<<grid, 256, GEMM_SMEM_>>>(At, Bt, C, Ct, N, K, ktout, bias, resid);
}

extern "C" void kernel_launch(void* const* d_in, const int* in_sizes, int n_in,
                              void* d_out, int out_size) {
    const int*   tokens    = (const int*)d_in[0];
    const int*   types     = (const int*)d_in[1];
    const int*   attn_mask = (const int*)d_in[2];
    const float* tok_emb   = (const float*)d_in[3];
    const float* type_emb  = (const float*)d_in[4];
    const float* pos_emb   = (const float*)d_in[5];
    const float* qkv_w     = (const float*)d_in[6];
    const float* out_w     = (const float*)d_in[7];
    const float* ln1_s     = (const float*)d_in[8];
    const float* ln1_b     = (const float*)d_in[9];
    const float* ln2_s     = (const float*)d_in[10];
    const float* ln2_b     = (const float*)d_in[11];
    const float* ff_w1     = (const float*)d_in[12];
    const float* ff_b1     = (const float*)d_in[13];
    const float* ff_w2     = (const float*)d_in[14];
    const float* ff_b2     = (const float*)d_in[15];
    const float* lnf_s     = (const float*)d_in[16];
    const float* lnf_b     = (const float*)d_in[17];
    const float* head_w    = (const float*)d_in[18];
    float* out = (float*)d_out;

    cudaFuncSetAttribute(k_mma_t<0, 0>, cudaFuncAttributeMaxDynamicSharedMemorySize, GEMM_SMEM_);
    cudaFuncSetAttribute(k_mma_t<1, 1>, cudaFuncAttributeMaxDynamicSharedMemorySize, GEMM_SMEM_);
    cudaFuncSetAttribute(k_attn, cudaFuncAttributeMaxDynamicSharedMemorySize, ATTN_SMEM_);

    float *x, *qkv;
    unsigned *ht, *yt, *ft, *wqt, *wot, *w1t, *w2t, *wht;
    cudaGetSymbolAddress((void**)&x, g_x);
    cudaGetSymbolAddress((void**)&qkv, g_qkv);
    cudaGetSymbolAddress((void**)&ht, g_ht);
    cudaGetSymbolAddress((void**)&yt, g_yt);
    cudaGetSymbolAddress((void**)&ft, g_ft);
    cudaGetSymbolAddress((void**)&wqt, g_wqt);
    cudaGetSymbolAddress((void**)&wot, g_wot);
    cudaGetSymbolAddress((void**)&w1t, g_w1t);
    cudaGetSymbolAddress((void**)&w2t, g_w2t);
    cudaGetSymbolAddress((void**)&wht, g_wht);

    for (int l = 0; l < NL_; l++) {
        k_cvt_w<<<(3 * D_ * D_ + 255) / 256, 256>>>(qkv_w + (size_t)l * 3 * D_ * D_,
                                                    wqt + (size_t)l * 3 * D_ * D_, 3 * D_, D_);
        k_cvt_w<<<(D_ * D_ + 255) / 256, 256>>>(out_w + (size_t)l * D_ * D_,
                                                wot + (size_t)l * D_ * D_, D_, D_);
        k_cvt_w<<<(FF_ * D_ + 255) / 256, 256>>>(ff_w1 + (size_t)l * FF_ * D_,
                                                 w1t + (size_t)l * FF_ * D_, FF_, D_);
        k_cvt_w<<<(D_ * FF_ + 255) / 256, 256>>>(ff_w2 + (size_t)l * D_ * FF_,
                                                 w2t + (size_t)l * D_ * FF_, D_, FF_);
    }
    k_cvt_w<<<(V_ * D_ + 255) / 256, 256>>>(head_w, wht, V_, D_);

    k_embed<<<(M_ * D_ + 255) / 256, 256>>>(tokens, types, tok_emb, type_emb, pos_emb);
    k_maskprep<<<1, 32>>>(tokens, attn_mask);

    for (int l = 0; l < NL_; l++) {
        size_t wq_off = (size_t)l * 3 * D_ * D_;
        size_t wo_off = (size_t)l * D_ * D_;
        size_t w1_off = (size_t)l * FF_ * D_;
        size_t w2_off = (size_t)l * D_ * FF_;

        k_ln_t<<<M_, 256>>>(x, ln1_s + l * D_, ln1_b + l * D_, ht);
        gemm_t(ht, wqt + wq_off, qkv, nullptr, 3 * D_, D_, 0, nullptr, nullptr, false);
        k_attn<<<dim3(L_ / 64, B_ * H_), 256, ATTN_SMEM_>>>(qkv);
        gemm_t(yt, wot + wo_off, x, nullptr, D_, D_, 0, nullptr, x, false);
        k_ln_t<<<M_, 256>>>(x, ln2_s + l * D_, ln2_b + l * D_, ht);
        gemm_t(ht, w1t + w1_off, nullptr, ft, FF_, D_, FF_, ff_b1 + l * FF_, nullptr, true);
        gemm_t(ft, w2t + w2_off, x, nullptr, D_, FF_, 0, ff_b2 + l * D_, x, false);
    }
    k_ln_t<<<M_, 256>>>(x, lnf_s, lnf_b, ht);
    gemm_t(ht, wht, out, nullptr, V_, D_, 0, nullptr, nullptr, false);
}